// round 8
// baseline (speedup 1.0000x reference)
#include <cuda_runtime.h>
#include <math.h>

#define NBLK 128
#define NTHR 512
typedef unsigned long long u64;

__device__ __align__(16) float g_fcT[2048 * 256];
__device__ __align__(16) float g_xT [512 * 256];
__device__ __align__(16) float g_x1T[512 * 256];
__device__ __align__(16) float g_hT [4 * 512 * 256];
__device__ __align__(16) float g_cT [2 * 512 * 256];
__device__ unsigned g_cnt = 0, g_gen = 0;

#define OFF_WMAP 0        // 32KB map weights (4 cols row-pair packed)
#define OFF_W0   32768    // 64KB lstm0
#define OFF_W1   98304    // 64KB lstm1
#define OFF_BS   163840   // biases
#define OFF_RED  164096   // 48KB reduce scratch [grp][idx][tid]
#define OFF_SG   213248   // 17408B gate tile [r][17]
#define SMEMSZ   230656

__device__ __forceinline__ u64 pk2(float x){ u64 d; asm("mov.b64 %0,{%1,%1};":"=l"(d):"f"(x)); return d; }
__device__ __forceinline__ void fma2(u64& d, u64 a, u64 b){ asm("fma.rn.f32x2 %0,%1,%2,%0;":"+l"(d):"l"(a),"l"(b)); }
__device__ __forceinline__ float2 up(u64 v){ float2 r; asm("mov.b64 {%0,%1},%2;":"=f"(r.x),"=f"(r.y):"l"(v)); return r; }
__device__ __forceinline__ float sigm(float x){ return 1.f/(1.f+__expf(-x)); }

__device__ __forceinline__ void gbar(){
    __syncthreads();
    if (threadIdx.x == 0){
        __threadfence();
        unsigned gen = *(volatile unsigned*)&g_gen;
        if (atomicAdd(&g_cnt, 1u) == NBLK - 1){ g_cnt = 0u; __threadfence(); atomicExch(&g_gen, gen + 1u); }
        else while (*(volatile unsigned*)&g_gen == gen) __nanosleep(32);
    }
    __syncthreads();
    __threadfence();
}

// one LSTM layer: block owns units u0..u0+3 (16 gate rows). Threads:
// kg=t>>7 (4-way K split), rh=(tp>>6)&1 (row half: 8 rows), bg=tp&63 (4 batches).
__device__ __forceinline__ void lstm_stage(int l, int p, const float* __restrict__ xT,
    const ulonglong2* __restrict__ wS, const float* __restrict__ bs, u64* red, float* sg, int u0)
{
    const int t = threadIdx.x, kg = t >> 7, tp = t & 127, rh = tp >> 6, bg = tp & 63, b0 = bg*4;
    const int half = kg >> 1, sub = kg & 1;
    const float* A = ((half ? g_hT + (size_t)(l*2+p)*131072 : xT) + (size_t)(sub*256)*256) + b0;
    const ulonglong2* W = wS + (size_t)(half*512 + sub*256)*4 + rh*2;

    u64 acc[4][4];
#pragma unroll
    for (int bi = 0; bi < 4; bi++)
#pragma unroll
        for (int j = 0; j < 4; j++) acc[bi][j] = 0ULL;

    float4 buf[4];
#pragma unroll
    for (int i = 0; i < 4; i++) buf[i] = *(const float4*)(A + (size_t)i*256);
#pragma unroll 1
    for (int kb = 0; kb < 256; kb += 4){
        float4 cur[4];
#pragma unroll
        for (int i = 0; i < 4; i++) cur[i] = buf[i];
        const int kn = (kb + 4) & 255;   // wraps at end: harmless dead prefetch
#pragma unroll
        for (int i = 0; i < 4; i++) buf[i] = *(const float4*)(A + (size_t)(kn + i)*256);
#pragma unroll
        for (int i = 0; i < 4; i++){
            const int k = kb + i;
            ulonglong2 wA = W[(size_t)k*4], wB = W[(size_t)k*4 + 1];
            u64 aa;
            aa = pk2(cur[i].x); fma2(acc[0][0],aa,wA.x); fma2(acc[0][1],aa,wA.y); fma2(acc[0][2],aa,wB.x); fma2(acc[0][3],aa,wB.y);
            aa = pk2(cur[i].y); fma2(acc[1][0],aa,wA.x); fma2(acc[1][1],aa,wA.y); fma2(acc[1][2],aa,wB.x); fma2(acc[1][3],aa,wB.y);
            aa = pk2(cur[i].z); fma2(acc[2][0],aa,wA.x); fma2(acc[2][1],aa,wA.y); fma2(acc[2][2],aa,wB.x); fma2(acc[2][3],aa,wB.y);
            aa = pk2(cur[i].w); fma2(acc[3][0],aa,wA.x); fma2(acc[3][1],aa,wA.y); fma2(acc[3][2],aa,wB.x); fma2(acc[3][3],aa,wB.y);
        }
    }
    if (kg){
        u64* rd = red + (size_t)(kg-1)*2048 + tp;
#pragma unroll
        for (int bi = 0; bi < 4; bi++)
#pragma unroll
            for (int j = 0; j < 4; j++) rd[(bi*4+j)*128] = acc[bi][j];
    }
    __syncthreads();
    if (!kg){
#pragma unroll
        for (int bi = 0; bi < 4; bi++){
            int r = b0 + bi;
#pragma unroll
            for (int j = 0; j < 4; j++){
                float2 v = up(acc[bi][j]);
#pragma unroll
                for (int g = 0; g < 3; g++){
                    float2 x2 = up(red[(size_t)g*2048 + (bi*4+j)*128 + tp]);
                    v.x += x2.x; v.y += x2.y;
                }
                int rr = rh*8 + 2*j;
                sg[r*17 + rr]     = v.x + bs[rr];
                sg[r*17 + rr + 1] = v.y + bs[rr + 1];
            }
        }
    }
    __syncthreads();
    if (t < 256){
        const int ul = t >> 6, bq = t & 63, r = bq*4, u = u0 + ul;
        float4 th, tc, hv;
        float* thp = &th.x; float* tcp = &tc.x; float* hvp = &hv.x;
        size_t ci = (size_t)l*131072 + (size_t)u*256 + r;
        float4 cold = *(const float4*)(g_cT + ci);
        const float* cop = &cold.x;
#pragma unroll
        for (int i = 0; i < 4; i++){
            const float* gr = sg + (r+i)*17;
            float gi = gr[ul], gf = gr[4+ul], gg = gr[8+ul], go = gr[12+ul];
            float c2 = sigm(gf)*cop[i] + sigm(gi)*tanhf(gg);
            float h2 = sigm(go)*tanhf(c2);
            hvp[i] = h2; thp[i] = tanhf(h2); tcp[i] = tanhf(c2);
        }
        *(float4*)(g_cT + ci) = tc;
        *(float4*)(g_hT + (size_t)(l*2 + (p^1))*131072 + (size_t)u*256 + r) = th;
        if (l == 0) *(float4*)(g_x1T + (size_t)u*256 + r) = hv;
#pragma unroll
        for (int i = 0; i < 4; i++){
            int rr = l*128 + ((r+i) >> 1), ch = ((r+i) & 1)*1024 + u;
            g_fcT[(size_t)ch*256 + rr] = thp[i];
            g_fcT[(size_t)(ch + 512)*256 + rr] = tcp[i];
        }
    }
}

extern "C" __global__ void __launch_bounds__(NTHR, 1)
dec_kernel(const float* __restrict__ latent, const float* __restrict__ fc_w,
    const float* __restrict__ fc_b, const float* __restrict__ map_w, const float* __restrict__ map_b,
    const float* __restrict__ wih0, const float* __restrict__ whh0, const float* __restrict__ bih0,
    const float* __restrict__ bhh0, const float* __restrict__ wih1, const float* __restrict__ whh1,
    const float* __restrict__ bih1, const float* __restrict__ bhh1, float* __restrict__ out)
{
    extern __shared__ unsigned char smem[];
    float* wmapF = (float*)(smem + OFF_WMAP);
    float* w0F   = (float*)(smem + OFF_W0);
    float* w1F   = (float*)(smem + OFF_W1);
    float* bs    = (float*)(smem + OFF_BS);
    u64*   red   = (u64*)  (smem + OFF_RED);
    float* sg    = (float*)(smem + OFF_SG);
    const int t = threadIdx.x, blk = blockIdx.x, u0 = blk*4, j0 = blk*4;

    for (int idx = t; idx < 2048*4; idx += NTHR){
        int k = idx >> 2, jl = idx & 3;
        wmapF[idx] = map_w[(size_t)(j0 + jl)*2048 + k];
    }
    for (int idx = t; idx < 1024*16; idx += NTHR){
        int k = idx >> 4, rr = idx & 15, row = (rr >> 2)*512 + u0 + (rr & 3);
        w0F[idx] = k < 512 ? wih0[(size_t)row*512 + k] : whh0[(size_t)row*512 + k - 512];
        w1F[idx] = k < 512 ? wih1[(size_t)row*512 + k] : whh1[(size_t)row*512 + k - 512];
    }
    if (t < 16){ int row = (t >> 2)*512 + u0 + (t & 3); bs[t] = bih0[row] + bhh0[row]; bs[16 + t] = bih1[row] + bhh1[row]; }
    if (t < 4) bs[32 + t] = map_b[j0 + t];
    __syncthreads();

    // ---- init: dec = tanh(latent @ fc_w.T + fc_b) ----
    {
        float* sL = (float*)red;
        int b0 = blk*2;
        for (int idx = t; idx < 512; idx += NTHR)
            sL[idx] = latent[(size_t)(b0 + (idx >> 8))*256 + (idx & 255)];
        __syncthreads();
        int bi = t >> 8, jb = (t & 255)*8, b = b0 + bi;
        const float* la = sL + bi*256;
        for (int m = 0; m < 8; m++){
            int jj = jb + m; float s = fc_b[jj];
            const float4* wr = (const float4*)(fc_w + (size_t)jj*256);
#pragma unroll 4
            for (int k4 = 0; k4 < 64; k4++){
                float4 w = wr[k4];
                s += la[k4*4]*w.x + la[k4*4+1]*w.y + la[k4*4+2]*w.z + la[k4*4+3]*w.w;
            }
            float val = tanhf(s);
            int l = b >> 7, b2 = ((b & 127)*2 + (jj >> 10)), jj2 = jj & 1023;
            if (jj2 < 512) g_hT[(size_t)(l*2)*131072 + (size_t)jj2*256 + b2] = val;
            else           g_cT[(size_t)l*131072 + (size_t)(jj2 - 512)*256 + b2] = val;
            int rr = l*128 + (b2 >> 1);
            g_fcT[(size_t)((b2 & 1)*1024 + jj2)*256 + rr] = val;
        }
        __syncthreads();
    }
    gbar();

    // ================= 256 sequential steps =================
    for (int step = 0; step < 256; step++){
        int p = step & 1;
        // ---- map: 4 cols, K=2048 split 8-way; threads: kg=t>>6, bg=t&63 (4 batches) ----
        {
            const int kg = t >> 6, bg = t & 63, b0 = bg*4;
            u64 acc[4][2];
#pragma unroll
            for (int bi = 0; bi < 4; bi++){ acc[bi][0] = 0ULL; acc[bi][1] = 0ULL; }
            const float* A = g_fcT + (size_t)(kg*256)*256 + b0;
            const ulonglong2* W = (const ulonglong2*)wmapF + kg*256;

            float4 buf[4];
#pragma unroll
            for (int i = 0; i < 4; i++) buf[i] = *(const float4*)(A + (size_t)i*256);
#pragma unroll 1
            for (int kb = 0; kb < 256; kb += 4){
                float4 cur[4];
#pragma unroll
                for (int i = 0; i < 4; i++) cur[i] = buf[i];
                const int kn = (kb + 4) & 255;
#pragma unroll
                for (int i = 0; i < 4; i++) buf[i] = *(const float4*)(A + (size_t)(kn + i)*256);
#pragma unroll
                for (int i = 0; i < 4; i++){
                    ulonglong2 w = W[kb + i];
                    u64 aa;
                    aa = pk2(cur[i].x); fma2(acc[0][0],aa,w.x); fma2(acc[0][1],aa,w.y);
                    aa = pk2(cur[i].y); fma2(acc[1][0],aa,w.x); fma2(acc[1][1],aa,w.y);
                    aa = pk2(cur[i].z); fma2(acc[2][0],aa,w.x); fma2(acc[2][1],aa,w.y);
                    aa = pk2(cur[i].w); fma2(acc[3][0],aa,w.x); fma2(acc[3][1],aa,w.y);
                }
            }
            if (kg){
                u64* rd = red + (size_t)(kg-1)*512 + bg;
#pragma unroll
                for (int bi = 0; bi < 4; bi++){ rd[(bi*2)*64] = acc[bi][0]; rd[(bi*2+1)*64] = acc[bi][1]; }
            }
            __syncthreads();
            if (!kg){
                float o[4][4];
#pragma unroll
                for (int bi = 0; bi < 4; bi++){
                    float2 v0 = up(acc[bi][0]), v1 = up(acc[bi][1]);
#pragma unroll
                    for (int g = 0; g < 7; g++){
                        float2 p0 = up(red[(size_t)g*512 + (bi*2)*64 + bg]);
                        float2 p1 = up(red[(size_t)g*512 + (bi*2+1)*64 + bg]);
                        v0.x += p0.x; v0.y += p0.y; v1.x += p1.x; v1.y += p1.y;
                    }
                    o[bi][0] = sigm(v0.x + bs[32]); o[bi][1] = sigm(v0.y + bs[33]);
                    o[bi][2] = sigm(v1.x + bs[34]); o[bi][3] = sigm(v1.y + bs[35]);
                    *(float4*)(out + ((size_t)step*256 + b0 + bi)*512 + j0) =
                        make_float4(o[bi][0], o[bi][1], o[bi][2], o[bi][3]);
                }
#pragma unroll
                for (int c = 0; c < 4; c++)
                    *(float4*)(g_xT + (size_t)(j0 + c)*256 + b0) =
                        make_float4(o[0][c], o[1][c], o[2][c], o[3][c]);
            }
        }
        gbar();
        lstm_stage(0, p, g_xT,  (const ulonglong2*)w0F, bs,      red, sg, u0);
        gbar();
        lstm_stage(1, p, g_x1T, (const ulonglong2*)w1F, bs + 16, red, sg, u0);
        gbar();
    }
}

extern "C" void kernel_launch(void* const* d_in, const int* in_sizes, int n_in,
                              void* d_out, int out_size)
{
    cudaFuncSetAttribute(dec_kernel, cudaFuncAttributeMaxDynamicSharedMemorySize, SMEMSZ);
    dec_kernel<<<NBLK, NTHR, SMEMSZ>>>(
        (const float*)d_in[0], (const float*)d_in[1], (const float*)d_in[2],
        (const float*)d_in[3], (const float*)d_in[4], (const float*)d_in[5],
        (const float*)d_in[6], (const float*)d_in[7], (const float*)d_in[8],
        (const float*)d_in[9], (const float*)d_in[10], (const float*)d_in[11],
        (const float*)d_in[12], (float*)d_out);
}

// round 9
// speedup vs baseline: 1.1413x; 1.1413x over previous
#include <cuda_runtime.h>
#include <math.h>

#define NBLK 128
#define NTHR 512
typedef unsigned long long u64;

__device__ __align__(16) float g_fcT[2048 * 256];
__device__ __align__(16) float g_xT [512 * 256];
__device__ __align__(16) float g_x1T[512 * 256];
__device__ __align__(16) float g_hT [4 * 512 * 256];
__device__ __align__(16) float g_cT [2 * 512 * 256];
__device__ unsigned g_cnt = 0, g_gen = 0;

#define OFF_WMAP 0        // 32KB map weights (4 cols row-pair packed)
#define OFF_W0   32768    // 64KB lstm0
#define OFF_W1   98304    // 64KB lstm1
#define OFF_BS   163840   // biases
#define OFF_RED  164096   // 48KB reduce scratch [grp][idx][tid]
#define OFF_SG   213248   // 17408B gate tile [r][17]
#define SMEMSZ   230656

__device__ __forceinline__ u64 pk2(float x){ u64 d; asm("mov.b64 %0,{%1,%1};":"=l"(d):"f"(x)); return d; }
__device__ __forceinline__ void fma2(u64& d, u64 a, u64 b){ asm("fma.rn.f32x2 %0,%1,%2,%0;":"+l"(d):"l"(a),"l"(b)); }
__device__ __forceinline__ float2 up(u64 v){ float2 r; asm("mov.b64 {%0,%1},%2;":"=f"(r.x),"=f"(r.y):"l"(v)); return r; }
__device__ __forceinline__ float sigm(float x){ return 1.f/(1.f+__expf(-x)); }

__device__ __forceinline__ void gbar(){
    __syncthreads();
    if (threadIdx.x == 0){
        __threadfence();
        unsigned gen = *(volatile unsigned*)&g_gen;
        if (atomicAdd(&g_cnt, 1u) == NBLK - 1){ g_cnt = 0u; __threadfence(); atomicExch(&g_gen, gen + 1u); }
        else while (*(volatile unsigned*)&g_gen == gen) __nanosleep(32);
    }
    __syncthreads();
    __threadfence();
}

// one LSTM layer: block owns units u0..u0+3 (16 gate rows). Threads:
// kg=t>>7 (4-way K split), rh=(tp>>6)&1 (row half: 8 rows), bg=tp&63 (4 batches).
__device__ __forceinline__ void lstm_stage(int l, int p, const float* __restrict__ xT,
    const ulonglong2* __restrict__ wS, const float* __restrict__ bs, u64* red, float* sg, int u0)
{
    const int t = threadIdx.x, kg = t >> 7, tp = t & 127, rh = tp >> 6, bg = tp & 63, b0 = bg*4;
    const int half = kg >> 1, sub = kg & 1;
    const float4* Af = (const float4*)(((half ? g_hT + (size_t)(l*2+p)*131072 : xT)
                                        + (size_t)(sub*256)*256) + b0);   // stride 64 float4 per k
    const ulonglong2* W = wS + (size_t)(half*512 + sub*256)*4 + rh*2;

    u64 acc[4][4];
#pragma unroll
    for (int bi = 0; bi < 4; bi++)
#pragma unroll
        for (int j = 0; j < 4; j++) acc[bi][j] = 0ULL;

    float4 p0[4], p1[4];
#pragma unroll
    for (int i = 0; i < 4; i++) p0[i] = Af[(size_t)i*64];
#pragma unroll
    for (int i = 0; i < 4; i++) p1[i] = Af[(size_t)(4+i)*64];

#pragma unroll 1
    for (int kb = 0; kb < 256; kb += 8){
#pragma unroll
        for (int i = 0; i < 4; i++){
            const int k = kb + i;
            ulonglong2 wA = W[(size_t)k*4], wB = W[(size_t)k*4 + 1];
            u64 aa;
            aa = pk2(p0[i].x); fma2(acc[0][0],aa,wA.x); fma2(acc[0][1],aa,wA.y); fma2(acc[0][2],aa,wB.x); fma2(acc[0][3],aa,wB.y);
            aa = pk2(p0[i].y); fma2(acc[1][0],aa,wA.x); fma2(acc[1][1],aa,wA.y); fma2(acc[1][2],aa,wB.x); fma2(acc[1][3],aa,wB.y);
            aa = pk2(p0[i].z); fma2(acc[2][0],aa,wA.x); fma2(acc[2][1],aa,wA.y); fma2(acc[2][2],aa,wB.x); fma2(acc[2][3],aa,wB.y);
            aa = pk2(p0[i].w); fma2(acc[3][0],aa,wA.x); fma2(acc[3][1],aa,wA.y); fma2(acc[3][2],aa,wB.x); fma2(acc[3][3],aa,wB.y);
        }
        if (kb < 248){
#pragma unroll
            for (int i = 0; i < 4; i++) p0[i] = Af[(size_t)(kb + 8 + i)*64];
        }
#pragma unroll
        for (int i = 0; i < 4; i++){
            const int k = kb + 4 + i;
            ulonglong2 wA = W[(size_t)k*4], wB = W[(size_t)k*4 + 1];
            u64 aa;
            aa = pk2(p1[i].x); fma2(acc[0][0],aa,wA.x); fma2(acc[0][1],aa,wA.y); fma2(acc[0][2],aa,wB.x); fma2(acc[0][3],aa,wB.y);
            aa = pk2(p1[i].y); fma2(acc[1][0],aa,wA.x); fma2(acc[1][1],aa,wA.y); fma2(acc[1][2],aa,wB.x); fma2(acc[1][3],aa,wB.y);
            aa = pk2(p1[i].z); fma2(acc[2][0],aa,wA.x); fma2(acc[2][1],aa,wA.y); fma2(acc[2][2],aa,wB.x); fma2(acc[2][3],aa,wB.y);
            aa = pk2(p1[i].w); fma2(acc[3][0],aa,wA.x); fma2(acc[3][1],aa,wA.y); fma2(acc[3][2],aa,wB.x); fma2(acc[3][3],aa,wB.y);
        }
        if (kb < 248){
#pragma unroll
            for (int i = 0; i < 4; i++) p1[i] = Af[(size_t)(kb + 12 + i)*64];
        }
    }
    if (kg){
        u64* rd = red + (size_t)(kg-1)*2048 + tp;
#pragma unroll
        for (int bi = 0; bi < 4; bi++)
#pragma unroll
            for (int j = 0; j < 4; j++) rd[(bi*4+j)*128] = acc[bi][j];
    }
    __syncthreads();
    if (!kg){
#pragma unroll
        for (int bi = 0; bi < 4; bi++){
            int r = b0 + bi;
#pragma unroll
            for (int j = 0; j < 4; j++){
                float2 v = up(acc[bi][j]);
#pragma unroll
                for (int g = 0; g < 3; g++){
                    float2 x2 = up(red[(size_t)g*2048 + (bi*4+j)*128 + tp]);
                    v.x += x2.x; v.y += x2.y;
                }
                int rr = rh*8 + 2*j;
                sg[r*17 + rr]     = v.x + bs[rr];
                sg[r*17 + rr + 1] = v.y + bs[rr + 1];
            }
        }
    }
    __syncthreads();
    if (t < 256){
        const int ul = t >> 6, bq = t & 63, r = bq*4, u = u0 + ul;
        float4 th, tc, hv;
        float* thp = &th.x; float* tcp = &tc.x; float* hvp = &hv.x;
        size_t ci = (size_t)l*131072 + (size_t)u*256 + r;
        float4 cold = *(const float4*)(g_cT + ci);
        const float* cop = &cold.x;
#pragma unroll
        for (int i = 0; i < 4; i++){
            const float* gr = sg + (r+i)*17;
            float gi = gr[ul], gf = gr[4+ul], gg = gr[8+ul], go = gr[12+ul];
            float c2 = sigm(gf)*cop[i] + sigm(gi)*tanhf(gg);
            float h2 = sigm(go)*tanhf(c2);
            hvp[i] = h2; thp[i] = tanhf(h2); tcp[i] = tanhf(c2);
        }
        *(float4*)(g_cT + ci) = tc;
        *(float4*)(g_hT + (size_t)(l*2 + (p^1))*131072 + (size_t)u*256 + r) = th;
        if (l == 0) *(float4*)(g_x1T + (size_t)u*256 + r) = hv;
#pragma unroll
        for (int i = 0; i < 4; i++){
            int rr = l*128 + ((r+i) >> 1), ch = ((r+i) & 1)*1024 + u;
            g_fcT[(size_t)ch*256 + rr] = thp[i];
            g_fcT[(size_t)(ch + 512)*256 + rr] = tcp[i];
        }
    }
}

extern "C" __global__ void __launch_bounds__(NTHR, 1)
dec_kernel(const float* __restrict__ latent, const float* __restrict__ fc_w,
    const float* __restrict__ fc_b, const float* __restrict__ map_w, const float* __restrict__ map_b,
    const float* __restrict__ wih0, const float* __restrict__ whh0, const float* __restrict__ bih0,
    const float* __restrict__ bhh0, const float* __restrict__ wih1, const float* __restrict__ whh1,
    const float* __restrict__ bih1, const float* __restrict__ bhh1, float* __restrict__ out)
{
    extern __shared__ unsigned char smem[];
    float* wmapF = (float*)(smem + OFF_WMAP);
    float* w0F   = (float*)(smem + OFF_W0);
    float* w1F   = (float*)(smem + OFF_W1);
    float* bs    = (float*)(smem + OFF_BS);
    u64*   red   = (u64*)  (smem + OFF_RED);
    float* sg    = (float*)(smem + OFF_SG);
    const int t = threadIdx.x, blk = blockIdx.x, u0 = blk*4, j0 = blk*4;

    for (int idx = t; idx < 2048*4; idx += NTHR){
        int k = idx >> 2, jl = idx & 3;
        wmapF[idx] = map_w[(size_t)(j0 + jl)*2048 + k];
    }
    for (int idx = t; idx < 1024*16; idx += NTHR){
        int k = idx >> 4, rr = idx & 15, row = (rr >> 2)*512 + u0 + (rr & 3);
        w0F[idx] = k < 512 ? wih0[(size_t)row*512 + k] : whh0[(size_t)row*512 + k - 512];
        w1F[idx] = k < 512 ? wih1[(size_t)row*512 + k] : whh1[(size_t)row*512 + k - 512];
    }
    if (t < 16){ int row = (t >> 2)*512 + u0 + (t & 3); bs[t] = bih0[row] + bhh0[row]; bs[16 + t] = bih1[row] + bhh1[row]; }
    if (t < 4) bs[32 + t] = map_b[j0 + t];
    __syncthreads();

    // ---- init: dec = tanh(latent @ fc_w.T + fc_b) ----
    {
        float* sL = (float*)red;
        int b0 = blk*2;
        for (int idx = t; idx < 512; idx += NTHR)
            sL[idx] = latent[(size_t)(b0 + (idx >> 8))*256 + (idx & 255)];
        __syncthreads();
        int bi = t >> 8, jb = (t & 255)*8, b = b0 + bi;
        const float* la = sL + bi*256;
        for (int m = 0; m < 8; m++){
            int jj = jb + m; float s = fc_b[jj];
            const float4* wr = (const float4*)(fc_w + (size_t)jj*256);
#pragma unroll 4
            for (int k4 = 0; k4 < 64; k4++){
                float4 w = wr[k4];
                s += la[k4*4]*w.x + la[k4*4+1]*w.y + la[k4*4+2]*w.z + la[k4*4+3]*w.w;
            }
            float val = tanhf(s);
            int l = b >> 7, b2 = ((b & 127)*2 + (jj >> 10)), jj2 = jj & 1023;
            if (jj2 < 512) g_hT[(size_t)(l*2)*131072 + (size_t)jj2*256 + b2] = val;
            else           g_cT[(size_t)l*131072 + (size_t)(jj2 - 512)*256 + b2] = val;
            int rr = l*128 + (b2 >> 1);
            g_fcT[(size_t)((b2 & 1)*1024 + jj2)*256 + rr] = val;
        }
        __syncthreads();
    }
    gbar();

    // ================= 256 sequential steps =================
    for (int step = 0; step < 256; step++){
        int p = step & 1;
        // ---- map: 4 cols, K=2048 split 8-way; threads: kg=t>>6, bg=t&63 (4 batches) ----
        {
            const int kg = t >> 6, bg = t & 63, b0 = bg*4;
            u64 acc[4][2];
#pragma unroll
            for (int bi = 0; bi < 4; bi++){ acc[bi][0] = 0ULL; acc[bi][1] = 0ULL; }
            const float4* Af = (const float4*)(g_fcT + (size_t)(kg*256)*256 + b0);
            const ulonglong2* W = (const ulonglong2*)wmapF + kg*256;

            float4 p0[4], p1[4];
#pragma unroll
            for (int i = 0; i < 4; i++) p0[i] = Af[(size_t)i*64];
#pragma unroll
            for (int i = 0; i < 4; i++) p1[i] = Af[(size_t)(4+i)*64];

#pragma unroll 1
            for (int kb = 0; kb < 256; kb += 8){
#pragma unroll
                for (int i = 0; i < 4; i++){
                    ulonglong2 w = W[kb + i];
                    u64 aa;
                    aa = pk2(p0[i].x); fma2(acc[0][0],aa,w.x); fma2(acc[0][1],aa,w.y);
                    aa = pk2(p0[i].y); fma2(acc[1][0],aa,w.x); fma2(acc[1][1],aa,w.y);
                    aa = pk2(p0[i].z); fma2(acc[2][0],aa,w.x); fma2(acc[2][1],aa,w.y);
                    aa = pk2(p0[i].w); fma2(acc[3][0],aa,w.x); fma2(acc[3][1],aa,w.y);
                }
                if (kb < 248){
#pragma unroll
                    for (int i = 0; i < 4; i++) p0[i] = Af[(size_t)(kb + 8 + i)*64];
                }
#pragma unroll
                for (int i = 0; i < 4; i++){
                    ulonglong2 w = W[kb + 4 + i];
                    u64 aa;
                    aa = pk2(p1[i].x); fma2(acc[0][0],aa,w.x); fma2(acc[0][1],aa,w.y);
                    aa = pk2(p1[i].y); fma2(acc[1][0],aa,w.x); fma2(acc[1][1],aa,w.y);
                    aa = pk2(p1[i].z); fma2(acc[2][0],aa,w.x); fma2(acc[2][1],aa,w.y);
                    aa = pk2(p1[i].w); fma2(acc[3][0],aa,w.x); fma2(acc[3][1],aa,w.y);
                }
                if (kb < 248){
#pragma unroll
                    for (int i = 0; i < 4; i++) p1[i] = Af[(size_t)(kb + 12 + i)*64];
                }
            }
            if (kg){
                u64* rd = red + (size_t)(kg-1)*512 + bg;
#pragma unroll
                for (int bi = 0; bi < 4; bi++){ rd[(bi*2)*64] = acc[bi][0]; rd[(bi*2+1)*64] = acc[bi][1]; }
            }
            __syncthreads();
            if (!kg){
                float o[4][4];
#pragma unroll
                for (int bi = 0; bi < 4; bi++){
                    float2 v0 = up(acc[bi][0]), v1 = up(acc[bi][1]);
#pragma unroll
                    for (int g = 0; g < 7; g++){
                        float2 q0 = up(red[(size_t)g*512 + (bi*2)*64 + bg]);
                        float2 q1 = up(red[(size_t)g*512 + (bi*2+1)*64 + bg]);
                        v0.x += q0.x; v0.y += q0.y; v1.x += q1.x; v1.y += q1.y;
                    }
                    o[bi][0] = sigm(v0.x + bs[32]); o[bi][1] = sigm(v0.y + bs[33]);
                    o[bi][2] = sigm(v1.x + bs[34]); o[bi][3] = sigm(v1.y + bs[35]);
                    *(float4*)(out + ((size_t)step*256 + b0 + bi)*512 + j0) =
                        make_float4(o[bi][0], o[bi][1], o[bi][2], o[bi][3]);
                }
#pragma unroll
                for (int c = 0; c < 4; c++)
                    *(float4*)(g_xT + (size_t)(j0 + c)*256 + b0) =
                        make_float4(o[0][c], o[1][c], o[2][c], o[3][c]);
            }
        }
        gbar();
        lstm_stage(0, p, g_xT,  (const ulonglong2*)w0F, bs,      red, sg, u0);
        gbar();
        lstm_stage(1, p, g_x1T, (const ulonglong2*)w1F, bs + 16, red, sg, u0);
        gbar();
    }
}

extern "C" void kernel_launch(void* const* d_in, const int* in_sizes, int n_in,
                              void* d_out, int out_size)
{
    cudaFuncSetAttribute(dec_kernel, cudaFuncAttributeMaxDynamicSharedMemorySize, SMEMSZ);
    dec_kernel<<<NBLK, NTHR, SMEMSZ>>>(
        (const float*)d_in[0], (const float*)d_in[1], (const float*)d_in[2],
        (const float*)d_in[3], (const float*)d_in[4], (const float*)d_in[5],
        (const float*)d_in[6], (const float*)d_in[7], (const float*)d_in[8],
        (const float*)d_in[9], (const float*)d_in[10], (const float*)d_in[11],
        (const float*)d_in[12], (float*)d_out);
}

// round 10
// speedup vs baseline: 1.5497x; 1.3578x over previous
#include <cuda_runtime.h>
#include <math.h>

#define NBLK 128
#define NTHR 512
typedef unsigned int u32;

// activation tensors in A-fragment layout: tiles [bt][kt][128 floats]
__device__ __align__(16) float g_fcA[16*256*128];   // fc_in, K=2048
__device__ __align__(16) float g_xA [16*64*128];    // map out, K=512
__device__ __align__(16) float g_x1A[16*64*128];    // layer0 h2 (pre-tanh)
__device__ __align__(16) float g_hA [4][16*64*128]; // tanh(h) [l*2+parity]
__device__ __align__(16) float g_cT [2*512*256];    // c carry (fp32, linear)
__device__ unsigned g_cnt=0, g_gen=0;

#define OFF_WMAP 0        // 64KB map W (B-frag, 4 real cols + 4 zero)
#define OFF_WL0  65536    // 64KB lstm0 W (B-frag, 16 gate rows = 2 n-tiles)
#define OFF_WL1  131072   // 64KB lstm1 W
#define OFF_BS   196608   // biases
#define OFF_SG   196864   // 16 warps x 16x18 gate tiles (18432B)
#define SMEMSZ   215296

// A-frag index for value (k,b); Kt = K/8 tiles
__device__ __forceinline__ int afidx(int k, int b, int Kt){
    return (((b>>4)*Kt + (k>>3))<<7) + (((b&7)*4 + (k&3))<<2) + ((b>>3)&1) + (((k>>2)&1)<<1);
}
__device__ __forceinline__ float tf32r(float x){ u32 r; asm("cvt.rna.tf32.f32 %0,%1;":"=r"(r):"f"(x)); return __uint_as_float(r); }
__device__ __forceinline__ float sigm(float x){ return 1.f/(1.f+__expf(-x)); }

__device__ __forceinline__ void mma8(float* d, uint4 a, u32 b0, u32 b1){
    asm("mma.sync.aligned.m16n8k8.row.col.f32.tf32.tf32.f32 {%0,%1,%2,%3},{%4,%5,%6,%7},{%8,%9},{%0,%1,%2,%3};"
        : "+f"(d[0]),"+f"(d[1]),"+f"(d[2]),"+f"(d[3])
        : "r"(a.x),"r"(a.y),"r"(a.z),"r"(a.w),"r"(b0),"r"(b1));
}

__device__ __forceinline__ void gbar(){
    __syncthreads();
    if (threadIdx.x == 0){
        __threadfence();
        unsigned gen = *(volatile unsigned*)&g_gen;
        if (atomicAdd(&g_cnt,1u) == NBLK-1){ g_cnt=0u; __threadfence(); atomicExch(&g_gen, gen+1u); }
        else while (*(volatile unsigned*)&g_gen == gen) __nanosleep(32);
    }
    __syncthreads();
    __threadfence();
}

// 64 k-tiles, 2 n-tiles: W stride per kt = 128 floats (nt at +64)
__device__ __forceinline__ void gemm64x2(const uint4* A, const float* W, float* d){
    uint4 ab[4];
#pragma unroll
    for (int i=0;i<4;i++) ab[i]=A[i*32];
#pragma unroll 1
    for (int kt=0;kt<64;kt+=4){
#pragma unroll
        for (int i=0;i<4;i++){
            uint2 w0=*(const uint2*)(W+(kt+i)*128);
            uint2 w1=*(const uint2*)(W+(kt+i)*128+64);
            mma8(d,   ab[i], w0.x, w0.y);
            mma8(d+4, ab[i], w1.x, w1.y);
        }
        if (kt<60){
#pragma unroll
            for (int i=0;i<4;i++) ab[i]=A[(kt+4+i)*32];
        }
    }
}

__device__ __forceinline__ void lstm_phase(int l, int p, const float* xA, const float* wS,
    const float* bs16, float* sgw, int u0, int wt, int lane)
{
    float d[8]={0,0,0,0,0,0,0,0};
    const uint4* Ax=(const uint4*)(xA + wt*64*128)+lane;
    const uint4* Ah=(const uint4*)(g_hA[l*2+p] + wt*64*128)+lane;
    const float* W = wS + lane*2;
    gemm64x2(Ax, W, d);
    gemm64x2(Ah, W + 64*128, d);

    int r1=lane>>2, c=2*(lane&3);
    *(float2*)(sgw + r1*18 + c)        = make_float2(d[0],d[1]);
    *(float2*)(sgw + (r1+8)*18 + c)    = make_float2(d[2],d[3]);
    *(float2*)(sgw + r1*18 + 8 + c)    = make_float2(d[4],d[5]);
    *(float2*)(sgw + (r1+8)*18 + 8 + c)= make_float2(d[6],d[7]);
    __syncwarp();
    int u=lane>>3, br0=lane&7, j=u0+u;
#pragma unroll
    for (int i=0;i<2;i++){
        int br=br0+8*i, b=wt*16+br;
        const float* gr=sgw+br*18;
        float gi=gr[u]+bs16[u], gf=gr[4+u]+bs16[4+u], gg=gr[8+u]+bs16[8+u], go=gr[12+u]+bs16[12+u];
        size_t ci=(size_t)l*131072 + (size_t)j*256 + b;
        float c2=sigm(gf)*g_cT[ci]+sigm(gi)*tanhf(gg);
        float h2=sigm(go)*tanhf(c2);
        float th=tanhf(h2), tc=tanhf(c2);
        g_cT[ci]=tc;
        g_hA[l*2+(p^1)][afidx(j,b,64)]=tf32r(th);
        if (l==0) g_x1A[afidx(j,b,64)]=tf32r(h2);
        int rf=l*128+(b>>1), ch=(b&1)*1024+j;
        g_fcA[afidx(ch,rf,256)]=tf32r(th);
        g_fcA[afidx(ch+512,rf,256)]=tf32r(tc);
    }
}

extern "C" __global__ void __launch_bounds__(NTHR,1)
dec_kernel(const float* __restrict__ latent, const float* __restrict__ fc_w,
    const float* __restrict__ fc_b, const float* __restrict__ map_w, const float* __restrict__ map_b,
    const float* __restrict__ wih0, const float* __restrict__ whh0, const float* __restrict__ bih0,
    const float* __restrict__ bhh0, const float* __restrict__ wih1, const float* __restrict__ whh1,
    const float* __restrict__ bih1, const float* __restrict__ bhh1, float* __restrict__ out)
{
    extern __shared__ unsigned char smem[];
    float* wmapS=(float*)(smem+OFF_WMAP);
    float* w0S  =(float*)(smem+OFF_WL0);
    float* w1S  =(float*)(smem+OFF_WL1);
    float* bs   =(float*)(smem+OFF_BS);
    float* sg   =(float*)(smem+OFF_SG);
    const int t=threadIdx.x, blk=blockIdx.x, u0=blk*4, j0=blk*4;
    const int wt=t>>5, lane=t&31;
    float* sgw = sg + wt*288;

    // ---- weights -> smem, B-frag layout, tf32-rounded ----
    for (int idx=t; idx<16384; idx+=NTHR){           // map: idx = kt*64 + ln*2 + sl
        int kt=idx>>6, q=idx&63, ln=q>>1, sl=q&1;
        int nr=ln>>2, k=kt*8 + (ln&3) + sl*4;
        wmapS[idx] = (nr<4) ? tf32r(map_w[(size_t)(j0+nr)*2048 + k]) : 0.f;
    }
    for (int idx=t; idx<16384; idx+=NTHR){           // lstm: idx = kt*128 + nt*64 + ln*2 + sl
        int kt=idx>>7, rem=idx&127, nt=rem>>6, q=rem&63, ln=q>>1, sl=q&1;
        int nr=ln>>2, kr=(ln&3)+sl*4, k=kt*8+kr, rr=nt*8+nr;
        int row=(rr>>2)*512 + u0 + (rr&3);
        w0S[idx]=tf32r(k<512? wih0[(size_t)row*512+k] : whh0[(size_t)row*512+k-512]);
        w1S[idx]=tf32r(k<512? wih1[(size_t)row*512+k] : whh1[(size_t)row*512+k-512]);
    }
    if (t<16){ int row=(t>>2)*512+u0+(t&3); bs[t]=bih0[row]+bhh0[row]; bs[16+t]=bih1[row]+bhh1[row]; }
    if (t<4) bs[32+t]=map_b[j0+t];
    __syncthreads();

    // ---- init: dec = tanh(latent @ fc_w.T + fc_b), scatter to frag tensors ----
    {
        float* sL=sg;  int b0=blk*2;
        for (int idx=t; idx<512; idx+=NTHR)
            sL[idx]=latent[(size_t)(b0+(idx>>8))*256 + (idx&255)];
        __syncthreads();
        int bi=t>>8, jb=(t&255)*8, b=b0+bi;
        const float* la=sL+bi*256;
        for (int m=0;m<8;m++){
            int jj=jb+m; float s=fc_b[jj];
            const float4* wr=(const float4*)(fc_w+(size_t)jj*256);
#pragma unroll 4
            for (int k4=0;k4<64;k4++){
                float4 w=wr[k4];
                s += la[k4*4]*w.x + la[k4*4+1]*w.y + la[k4*4+2]*w.z + la[k4*4+3]*w.w;
            }
            float val=tanhf(s);
            int l=b>>7, b2=((b&127)*2 + (jj>>10)), jj2=jj&1023;
            if (jj2<512) g_hA[l*2][afidx(jj2,b2,64)]=tf32r(val);
            else         g_cT[(size_t)l*131072 + (size_t)(jj2-512)*256 + b2]=val;
            int rf=l*128+(b2>>1), ch=(b2&1)*1024+jj2;
            g_fcA[afidx(ch,rf,256)]=tf32r(val);
        }
        __syncthreads();
    }
    gbar();

    // ================= 256 sequential steps =================
    for (int step=0; step<256; step++){
        int p=step&1;
        // ---- map: per warp bt=wt, K=2048, 1 n-tile (4 real cols) ----
        {
            float d[4]={0,0,0,0};
            const uint4* A=(const uint4*)(g_fcA + wt*256*128)+lane;
            const float* W=wmapS + lane*2;
            uint4 ab[4];
#pragma unroll
            for (int i=0;i<4;i++) ab[i]=A[i*32];
#pragma unroll 1
            for (int kt=0;kt<256;kt+=4){
#pragma unroll
                for (int i=0;i<4;i++){
                    uint2 w=*(const uint2*)(W+(kt+i)*64);
                    mma8(d, ab[i], w.x, w.y);
                }
                if (kt<252){
#pragma unroll
                    for (int i=0;i<4;i++) ab[i]=A[(kt+4+i)*32];
                }
            }
            int c=2*(lane&3);
            if (c<4){
                int r1=lane>>2, b1=wt*16+r1, b2=b1+8;
                float o0=sigm(d[0]+bs[32+c]), o1=sigm(d[1]+bs[33+c]);
                float o2=sigm(d[2]+bs[32+c]), o3=sigm(d[3]+bs[33+c]);
                *(float2*)(out + ((size_t)step*256+b1)*512 + j0+c) = make_float2(o0,o1);
                *(float2*)(out + ((size_t)step*256+b2)*512 + j0+c) = make_float2(o2,o3);
                g_xA[afidx(j0+c,  b1,64)]=tf32r(o0);
                g_xA[afidx(j0+c+1,b1,64)]=tf32r(o1);
                g_xA[afidx(j0+c,  b2,64)]=tf32r(o2);
                g_xA[afidx(j0+c+1,b2,64)]=tf32r(o3);
            }
        }
        gbar();
        lstm_phase(0,p,g_xA,  w0S, bs,    sgw, u0, wt, lane);
        gbar();
        lstm_phase(1,p,g_x1A, w1S, bs+16, sgw, u0, wt, lane);
        gbar();
    }
}

extern "C" void kernel_launch(void* const* d_in, const int* in_sizes, int n_in,
                              void* d_out, int out_size)
{
    cudaFuncSetAttribute(dec_kernel, cudaFuncAttributeMaxDynamicSharedMemorySize, SMEMSZ);
    dec_kernel<<<NBLK, NTHR, SMEMSZ>>>(
        (const float*)d_in[0], (const float*)d_in[1], (const float*)d_in[2],
        (const float*)d_in[3], (const float*)d_in[4], (const float*)d_in[5],
        (const float*)d_in[6], (const float*)d_in[7], (const float*)d_in[8],
        (const float*)d_in[9], (const float*)d_in[10], (const float*)d_in[11],
        (const float*)d_in[12], (float*)d_out);
}

// round 11
// speedup vs baseline: 2.0585x; 1.3283x over previous
#include <cuda_runtime.h>
#include <math.h>

#define NBLK 128
#define NTHR 512
typedef unsigned int u32;

// activation tensors in A-fragment layout: tiles [bt][kt][128 floats]
__device__ __align__(16) float g_fcA[16*256*128];   // fc_in, K=2048
__device__ __align__(16) float g_xA [16*64*128];    // map out, K=512
__device__ __align__(16) float g_x1A[16*64*128];    // layer0 h2 (pre-tanh)
__device__ __align__(16) float g_hA [4][16*64*128]; // tanh(h) [l*2+parity]
__device__ __align__(16) float g_cT [2*512*256];    // c carry (fp32, linear)
__device__ unsigned g_cnt=0, g_gen=0;

#define OFF_WMAP 0        // 64KB map W (B-frag, 8 REAL cols)
#define OFF_WL0  65536    // 64KB lstm0 W (B-frag, 16 gate rows = 2 n-tiles)
#define OFF_WL1  131072   // 64KB lstm1 W
#define OFF_BS   196608   // biases
#define OFF_SG   196864   // warp gate tiles / map reduce scratch
#define SMEMSZ   215296

__device__ __forceinline__ int afidx(int k, int b, int Kt){
    return (((b>>4)*Kt + (k>>3))<<7) + (((b&7)*4 + (k&3))<<2) + ((b>>3)&1) + (((k>>2)&1)<<1);
}
__device__ __forceinline__ float tf32r(float x){ u32 r; asm("cvt.rna.tf32.f32 %0,%1;":"=r"(r):"f"(x)); return __uint_as_float(r); }
__device__ __forceinline__ float sigm(float x){ return 1.f/(1.f+__expf(-x)); }

__device__ __forceinline__ void mma8(float* d, uint4 a, u32 b0, u32 b1){
    asm("mma.sync.aligned.m16n8k8.row.col.f32.tf32.tf32.f32 {%0,%1,%2,%3},{%4,%5,%6,%7},{%8,%9},{%0,%1,%2,%3};"
        : "+f"(d[0]),"+f"(d[1]),"+f"(d[2]),"+f"(d[3])
        : "r"(a.x),"r"(a.y),"r"(a.z),"r"(a.w),"r"(b0),"r"(b1));
}

__device__ __forceinline__ void gbar(){
    __syncthreads();
    if (threadIdx.x == 0){
        __threadfence();
        unsigned gen = *(volatile unsigned*)&g_gen;
        if (atomicAdd(&g_cnt,1u) == NBLK-1){ g_cnt=0u; __threadfence(); atomicExch(&g_gen, gen+1u); }
        else while (*(volatile unsigned*)&g_gen == gen) __nanosleep(32);
    }
    __syncthreads();
    __threadfence();
}

// LSTM layer: block owns units u0..u0+3 (16 gate rows = 2 n-tiles); warp = one 16-batch tile.
// x-gemm and h-gemm interleaved: 8 LDG.128 in flight per warp.
__device__ __forceinline__ void lstm_phase(int l, int p, const float* xA, const float* wS,
    const float* bs16, float* sgw, int u0, int wt, int lane)
{
    float d[8]={0,0,0,0,0,0,0,0};
    const uint4* Ax=(const uint4*)(xA + wt*64*128)+lane;
    const uint4* Ah=(const uint4*)(g_hA[l*2+p] + wt*64*128)+lane;
    const float* Wx = wS + lane*2;
    const float* Wh = wS + 64*128 + lane*2;

    uint4 px[4], ph[4];
#pragma unroll
    for (int i=0;i<4;i++){ px[i]=Ax[i*32]; ph[i]=Ah[i*32]; }
#pragma unroll 1
    for (int kb=0; kb<64; kb+=4){
#pragma unroll
        for (int i=0;i<4;i++){
            const int k=kb+i;
            uint2 w0=*(const uint2*)(Wx+k*128);
            uint2 w1=*(const uint2*)(Wx+k*128+64);
            mma8(d,   px[i], w0.x, w0.y);
            mma8(d+4, px[i], w1.x, w1.y);
        }
        if (kb<60){
#pragma unroll
            for (int i=0;i<4;i++) px[i]=Ax[(kb+4+i)*32];
        }
#pragma unroll
        for (int i=0;i<4;i++){
            const int k=kb+i;
            uint2 w0=*(const uint2*)(Wh+k*128);
            uint2 w1=*(const uint2*)(Wh+k*128+64);
            mma8(d,   ph[i], w0.x, w0.y);
            mma8(d+4, ph[i], w1.x, w1.y);
        }
        if (kb<60){
#pragma unroll
            for (int i=0;i<4;i++) ph[i]=Ah[(kb+4+i)*32];
        }
    }

    int r1=lane>>2, c=2*(lane&3);
    *(float2*)(sgw + r1*18 + c)        = make_float2(d[0],d[1]);
    *(float2*)(sgw + (r1+8)*18 + c)    = make_float2(d[2],d[3]);
    *(float2*)(sgw + r1*18 + 8 + c)    = make_float2(d[4],d[5]);
    *(float2*)(sgw + (r1+8)*18 + 8 + c)= make_float2(d[6],d[7]);
    __syncwarp();
    int u=lane>>3, br0=lane&7, j=u0+u;
#pragma unroll
    for (int i=0;i<2;i++){
        int br=br0+8*i, b=wt*16+br;
        const float* gr=sgw+br*18;
        float gi=gr[u]+bs16[u], gf=gr[4+u]+bs16[4+u], gg=gr[8+u]+bs16[8+u], go=gr[12+u]+bs16[12+u];
        size_t ci=(size_t)l*131072 + (size_t)j*256 + b;
        float c2=sigm(gf)*g_cT[ci]+sigm(gi)*tanhf(gg);
        float h2=sigm(go)*tanhf(c2);
        float th=tanhf(h2), tc=tanhf(c2);
        g_cT[ci]=tc;
        g_hA[l*2+(p^1)][afidx(j,b,64)]=tf32r(th);
        if (l==0) g_x1A[afidx(j,b,64)]=tf32r(h2);
        int rf=l*128+(b>>1), ch=(b&1)*1024+j;
        g_fcA[afidx(ch,rf,256)]=tf32r(th);
        g_fcA[afidx(ch+512,rf,256)]=tf32r(tc);
    }
}

extern "C" __global__ void __launch_bounds__(NTHR,1)
dec_kernel(const float* __restrict__ latent, const float* __restrict__ fc_w,
    const float* __restrict__ fc_b, const float* __restrict__ map_w, const float* __restrict__ map_b,
    const float* __restrict__ wih0, const float* __restrict__ whh0, const float* __restrict__ bih0,
    const float* __restrict__ bhh0, const float* __restrict__ wih1, const float* __restrict__ whh1,
    const float* __restrict__ bih1, const float* __restrict__ bhh1, float* __restrict__ out)
{
    extern __shared__ unsigned char smem[];
    float* wmapS=(float*)(smem+OFF_WMAP);
    float* w0S  =(float*)(smem+OFF_WL0);
    float* w1S  =(float*)(smem+OFF_WL1);
    float* bs   =(float*)(smem+OFF_BS);
    float* sg   =(float*)(smem+OFF_SG);
    const int t=threadIdx.x, blk=blockIdx.x, u0=blk*4;
    const int wt=t>>5, lane=t&31;
    const int j0m=(blk>>1)*8, bgrp=blk&1;   // map: 8 cols x 128 batches
    float* sgw = sg + wt*288;

    // ---- weights -> smem, B-frag layout, tf32-rounded ----
    for (int idx=t; idx<16384; idx+=NTHR){           // map: idx = kt*64 + ln*2 + sl
        int kt=idx>>6, q=idx&63, ln=q>>1, sl=q&1;
        int nr=ln>>2, k=kt*8 + (ln&3) + sl*4;
        wmapS[idx] = tf32r(map_w[(size_t)(j0m+nr)*2048 + k]);
    }
    for (int idx=t; idx<16384; idx+=NTHR){           // lstm: idx = kt*128 + nt*64 + ln*2 + sl
        int kt=idx>>7, rem=idx&127, nt=rem>>6, q=rem&63, ln=q>>1, sl=q&1;
        int nr=ln>>2, kr=(ln&3)+sl*4, k=kt*8+kr, rr=nt*8+nr;
        int row=(rr>>2)*512 + u0 + (rr&3);
        w0S[idx]=tf32r(k<512? wih0[(size_t)row*512+k] : whh0[(size_t)row*512+k-512]);
        w1S[idx]=tf32r(k<512? wih1[(size_t)row*512+k] : whh1[(size_t)row*512+k-512]);
    }
    if (t<16){ int row=(t>>2)*512+u0+(t&3); bs[t]=bih0[row]+bhh0[row]; bs[16+t]=bih1[row]+bhh1[row]; }
    if (t<8) bs[32+t]=map_b[j0m+t];
    __syncthreads();

    // ---- init: dec = tanh(latent @ fc_w.T + fc_b), scatter to frag tensors ----
    {
        float* sL=sg;  int b0=blk*2;
        for (int idx=t; idx<512; idx+=NTHR)
            sL[idx]=latent[(size_t)(b0+(idx>>8))*256 + (idx&255)];
        __syncthreads();
        int bi=t>>8, jb=(t&255)*8, b=b0+bi;
        const float* la=sL+bi*256;
        for (int m=0;m<8;m++){
            int jj=jb+m; float s=fc_b[jj];
            const float4* wr=(const float4*)(fc_w+(size_t)jj*256);
#pragma unroll 4
            for (int k4=0;k4<64;k4++){
                float4 w=wr[k4];
                s += la[k4*4]*w.x + la[k4*4+1]*w.y + la[k4*4+2]*w.z + la[k4*4+3]*w.w;
            }
            float val=tanhf(s);
            int l=b>>7, b2=((b&127)*2 + (jj>>10)), jj2=jj&1023;
            if (jj2<512) g_hA[l*2][afidx(jj2,b2,64)]=tf32r(val);
            else         g_cT[(size_t)l*131072 + (size_t)(jj2-512)*256 + b2]=val;
            int rf=l*128+(b2>>1), ch=(b2&1)*1024+jj2;
            g_fcA[afidx(ch,rf,256)]=tf32r(val);
        }
        __syncthreads();
    }
    gbar();

    // ================= 256 sequential steps =================
    for (int step=0; step<256; step++){
        int p=step&1;
        // ---- map: 8 cols x 128 batches; warp = (khalf kh, batch tile tt); K split 2-way ----
        {
            const int tt = wt & 7, kh = wt >> 3;
            const int bt = bgrp*8 + tt;          // global 16-batch tile
            float d[4]={0,0,0,0};
            const uint4* A=(const uint4*)(g_fcA + ((size_t)bt*256 + kh*128)*128)+lane;
            const float* W=wmapS + kh*128*64 + lane*2;
            uint4 p0[4], p1[4];
#pragma unroll
            for (int i=0;i<4;i++) p0[i]=A[i*32];
#pragma unroll
            for (int i=0;i<4;i++) p1[i]=A[(4+i)*32];
#pragma unroll 1
            for (int kb=0;kb<128;kb+=8){
#pragma unroll
                for (int i=0;i<4;i++){
                    uint2 w=*(const uint2*)(W+(kb+i)*64);
                    mma8(d, p0[i], w.x, w.y);
                }
                if (kb<120){
#pragma unroll
                    for (int i=0;i<4;i++) p0[i]=A[(kb+8+i)*32];
                }
#pragma unroll
                for (int i=0;i<4;i++){
                    uint2 w=*(const uint2*)(W+(kb+4+i)*64);
                    mma8(d, p1[i], w.x, w.y);
                }
                if (kb<120){
#pragma unroll
                    for (int i=0;i<4;i++) p1[i]=A[(kb+12+i)*32];
                }
            }
            float* rg = sg;   // 8 tiles x 128 floats = 4KB scratch
            if (kh) *(float4*)(rg + tt*128 + lane*4) = make_float4(d[0],d[1],d[2],d[3]);
            __syncthreads();
            if (!kh){
                float4 q = *(const float4*)(rg + tt*128 + lane*4);
                d[0]+=q.x; d[1]+=q.y; d[2]+=q.z; d[3]+=q.w;
                int r1=lane>>2, c=2*(lane&3);
                int b1 = bgrp*128 + tt*16 + r1, b2 = b1+8;
                float o0=sigm(d[0]+bs[32+c]), o1=sigm(d[1]+bs[33+c]);
                float o2=sigm(d[2]+bs[32+c]), o3=sigm(d[3]+bs[33+c]);
                *(float2*)(out + ((size_t)step*256+b1)*512 + j0m+c) = make_float2(o0,o1);
                *(float2*)(out + ((size_t)step*256+b2)*512 + j0m+c) = make_float2(o2,o3);
                g_xA[afidx(j0m+c,  b1,64)]=tf32r(o0);
                g_xA[afidx(j0m+c+1,b1,64)]=tf32r(o1);
                g_xA[afidx(j0m+c,  b2,64)]=tf32r(o2);
                g_xA[afidx(j0m+c+1,b2,64)]=tf32r(o3);
            }
        }
        gbar();
        lstm_phase(0,p,g_xA,  w0S, bs,    sgw, u0, wt, lane);
        gbar();
        lstm_phase(1,p,g_x1A, w1S, bs+16, sgw, u0, wt, lane);
        gbar();
    }
}

extern "C" void kernel_launch(void* const* d_in, const int* in_sizes, int n_in,
                              void* d_out, int out_size)
{
    cudaFuncSetAttribute(dec_kernel, cudaFuncAttributeMaxDynamicSharedMemorySize, SMEMSZ);
    dec_kernel<<<NBLK, NTHR, SMEMSZ>>>(
        (const float*)d_in[0], (const float*)d_in[1], (const float*)d_in[2],
        (const float*)d_in[3], (const float*)d_in[4], (const float*)d_in[5],
        (const float*)d_in[6], (const float*)d_in[7], (const float*)d_in[8],
        (const float*)d_in[9], (const float*)d_in[10], (const float*)d_in[11],
        (const float*)d_in[12], (float*)d_out);
}

// round 12
// speedup vs baseline: 2.4059x; 1.1688x over previous
#include <cuda_runtime.h>
#include <cuda_fp16.h>
#include <math.h>

#define NBLK 128
#define NTHR 512
typedef unsigned int u32;

// activation tensors in fp16 A-fragment layout: tiles [bt][kt16][256 halves]
__device__ __align__(16) __half g_fcA[16*128*256];   // fc_in, K=2048
__device__ __align__(16) __half g_xA [16*32*256];    // map out, K=512
__device__ __align__(16) __half g_x1A[16*32*256];    // layer0 h2 (pre-tanh)
__device__ __align__(16) __half g_hA [4][16*32*256]; // tanh(h) [l*2+parity]
__device__ __align__(16) float  g_cT [2*512*256];    // c carry (fp32, linear)
__device__ unsigned g_cnt=0, g_gen=0;

#define OFF_WMAP 0        // 32KB map W (B-frag halves, 8 real cols)
#define OFF_WL0  32768    // 32KB lstm0 W (2 n-tiles)
#define OFF_WL1  65536    // 32KB lstm1 W
#define OFF_BS   98304    // biases (fp32)
#define OFF_SG   98560    // 16 warps x 16x18 fp32 gate tiles / map reduce scratch
#define SMEMSZ   116992

// half index of value (k,b) in A-frag storage; Kt16 = K/16
__device__ __forceinline__ int afx(int k, int b, int Kt16){
    return (((b>>4)*Kt16 + (k>>4))<<8) + (((b&7)*4 + ((k&7)>>1))<<3)
         + (((k>>3)&1)<<2) + (((b>>3)&1)<<1) + (k&1);
}
__device__ __forceinline__ float sigm(float x){ return 1.f/(1.f+__expf(-x)); }

__device__ __forceinline__ void mma16(float* d, uint4 a, uint2 b){
    asm("mma.sync.aligned.m16n8k16.row.col.f32.f16.f16.f32 {%0,%1,%2,%3},{%4,%5,%6,%7},{%8,%9},{%0,%1,%2,%3};"
        : "+f"(d[0]),"+f"(d[1]),"+f"(d[2]),"+f"(d[3])
        : "r"(a.x),"r"(a.y),"r"(a.z),"r"(a.w),"r"(b.x),"r"(b.y));
}

__device__ __forceinline__ void gbar(){
    __syncthreads();
    if (threadIdx.x == 0){
        __threadfence();
        unsigned gen = *(volatile unsigned*)&g_gen;
        if (atomicAdd(&g_cnt,1u) == NBLK-1){ g_cnt=0u; __threadfence(); atomicExch(&g_gen, gen+1u); }
        else while (*(volatile unsigned*)&g_gen == gen) __nanosleep(32);
    }
    __syncthreads();
    __threadfence();
}

// LSTM layer: block owns units u0..u0+3 (16 gate rows = 2 n-tiles); warp = one 16-batch tile.
// x-gemm (kt 0..31) and h-gemm (kt 32..63) interleaved, 8 LDG.128 in flight.
__device__ __forceinline__ void lstm_phase(int l, int p, const __half* xA, const __half* wS,
    const float* bs16, float* sgw, int u0, int wt, int lane)
{
    float d[8]={0,0,0,0,0,0,0,0};
    const uint4* Ax=(const uint4*)(xA + wt*32*256)+lane;
    const uint4* Ah=(const uint4*)(g_hA[l*2+p] + wt*32*256)+lane;
    const __half* W = wS + lane*4;

    uint4 px[4], ph[4];
#pragma unroll
    for (int i=0;i<4;i++){ px[i]=Ax[i*32]; ph[i]=Ah[i*32]; }
#pragma unroll 1
    for (int kb=0; kb<32; kb+=4){
#pragma unroll
        for (int i=0;i<4;i++){
            const int kt=kb+i;
            uint2 w0=*(const uint2*)(W + (kt*2+0)*128);
            uint2 w1=*(const uint2*)(W + (kt*2+1)*128);
            mma16(d,   px[i], w0);
            mma16(d+4, px[i], w1);
        }
        if (kb<28){
#pragma unroll
            for (int i=0;i<4;i++) px[i]=Ax[(kb+4+i)*32];
        }
#pragma unroll
        for (int i=0;i<4;i++){
            const int kt=32+kb+i;
            uint2 w0=*(const uint2*)(W + (kt*2+0)*128);
            uint2 w1=*(const uint2*)(W + (kt*2+1)*128);
            mma16(d,   ph[i], w0);
            mma16(d+4, ph[i], w1);
        }
        if (kb<28){
#pragma unroll
            for (int i=0;i<4;i++) ph[i]=Ah[(kb+4+i)*32];
        }
    }

    int r1=lane>>2, c=2*(lane&3);
    *(float2*)(sgw + r1*18 + c)        = make_float2(d[0],d[1]);
    *(float2*)(sgw + (r1+8)*18 + c)    = make_float2(d[2],d[3]);
    *(float2*)(sgw + r1*18 + 8 + c)    = make_float2(d[4],d[5]);
    *(float2*)(sgw + (r1+8)*18 + 8 + c)= make_float2(d[6],d[7]);
    __syncwarp();
    int u=lane>>3, br0=lane&7, j=u0+u;
#pragma unroll
    for (int i=0;i<2;i++){
        int br=br0+8*i, b=wt*16+br;
        const float* gr=sgw+br*18;
        float gi=gr[u]+bs16[u], gf=gr[4+u]+bs16[4+u], gg=gr[8+u]+bs16[8+u], go=gr[12+u]+bs16[12+u];
        size_t ci=(size_t)l*131072 + (size_t)j*256 + b;
        float c2=sigm(gf)*g_cT[ci]+sigm(gi)*tanhf(gg);
        float h2=sigm(go)*tanhf(c2);
        float th=tanhf(h2), tc=tanhf(c2);
        g_cT[ci]=tc;
        g_hA[l*2+(p^1)][afx(j,b,32)]=__float2half(th);
        if (l==0) g_x1A[afx(j,b,32)]=__float2half(h2);
        int rf=l*128+(b>>1), ch=(b&1)*1024+j;
        g_fcA[afx(ch,rf,128)]=__float2half(th);
        g_fcA[afx(ch+512,rf,128)]=__float2half(tc);
    }
}

extern "C" __global__ void __launch_bounds__(NTHR,1)
dec_kernel(const float* __restrict__ latent, const float* __restrict__ fc_w,
    const float* __restrict__ fc_b, const float* __restrict__ map_w, const float* __restrict__ map_b,
    const float* __restrict__ wih0, const float* __restrict__ whh0, const float* __restrict__ bih0,
    const float* __restrict__ bhh0, const float* __restrict__ wih1, const float* __restrict__ whh1,
    const float* __restrict__ bih1, const float* __restrict__ bhh1, float* __restrict__ out)
{
    extern __shared__ unsigned char smem[];
    __half* wmapS=(__half*)(smem+OFF_WMAP);
    __half* w0S  =(__half*)(smem+OFF_WL0);
    __half* w1S  =(__half*)(smem+OFF_WL1);
    float*  bs   =(float*) (smem+OFF_BS);
    float*  sg   =(float*) (smem+OFF_SG);
    const int t=threadIdx.x, blk=blockIdx.x, u0=blk*4;
    const int wt=t>>5, lane=t&31;
    const int j0m=(blk>>1)*8, bgrp=blk&1;   // map: 8 cols x 128 batches
    float* sgw = sg + wt*288;

    // ---- weights -> smem, B-frag half layout ----
    for (int idx=t; idx<16384; idx+=NTHR){           // map: idx = kt*128 + ln*4 + sl*2 + klo
        int kt=idx>>7, r2=idx&127, ln=r2>>2, q=r2&3, sl=q>>1, klo=q&1;
        int g=ln>>2, tn=ln&3;
        int k=kt*16 + sl*8 + tn*2 + klo;
        wmapS[idx] = __float2half(map_w[(size_t)(j0m+g)*2048 + k]);
    }
    for (int idx=t; idx<16384; idx+=NTHR){           // lstm: idx = (kt*2+nt)*128 + ln*4 + sl*2 + klo
        int kt=idx>>8, rem=idx&255, nt=rem>>7, r2=rem&127, ln=r2>>2, q=r2&3, sl=q>>1, klo=q&1;
        int g=ln>>2, tn=ln&3;
        int rr=nt*8+g, k=kt*16 + sl*8 + tn*2 + klo;
        int row=(rr>>2)*512 + u0 + (rr&3);
        w0S[idx]=__float2half(k<512? wih0[(size_t)row*512+k] : whh0[(size_t)row*512+k-512]);
        w1S[idx]=__float2half(k<512? wih1[(size_t)row*512+k] : whh1[(size_t)row*512+k-512]);
    }
    if (t<16){ int row=(t>>2)*512+u0+(t&3); bs[t]=bih0[row]+bhh0[row]; bs[16+t]=bih1[row]+bhh1[row]; }
    if (t<8) bs[32+t]=map_b[j0m+t];
    __syncthreads();

    // ---- init: dec = tanh(latent @ fc_w.T + fc_b), scatter to frag tensors ----
    {
        float* sL=sg;  int b0=blk*2;
        for (int idx=t; idx<512; idx+=NTHR)
            sL[idx]=latent[(size_t)(b0+(idx>>8))*256 + (idx&255)];
        __syncthreads();
        int bi=t>>8, jb=(t&255)*8, b=b0+bi;
        const float* la=sL+bi*256;
        for (int m=0;m<8;m++){
            int jj=jb+m; float s=fc_b[jj];
            const float4* wr=(const float4*)(fc_w+(size_t)jj*256);
#pragma unroll 4
            for (int k4=0;k4<64;k4++){
                float4 w=wr[k4];
                s += la[k4*4]*w.x + la[k4*4+1]*w.y + la[k4*4+2]*w.z + la[k4*4+3]*w.w;
            }
            float val=tanhf(s);
            int l=b>>7, b2=((b&127)*2 + (jj>>10)), jj2=jj&1023;
            if (jj2<512) g_hA[l*2][afx(jj2,b2,32)]=__float2half(val);
            else         g_cT[(size_t)l*131072 + (size_t)(jj2-512)*256 + b2]=val;
            int rf=l*128+(b2>>1), ch=(b2&1)*1024+jj2;
            g_fcA[afx(ch,rf,128)]=__float2half(val);
        }
        __syncthreads();
    }
    gbar();

    // ================= 256 sequential steps =================
    for (int step=0; step<256; step++){
        int p=step&1;
        // ---- map: 8 cols x 128 batches; warp = (khalf kh, batch tile tt); K split 2-way ----
        {
            const int tt = wt & 7, kh = wt >> 3;
            const int bt = bgrp*8 + tt;
            float d[4]={0,0,0,0};
            const uint4* A=(const uint4*)(g_fcA + ((size_t)bt*128 + kh*64)*256)+lane;
            const __half* W=wmapS + kh*64*128 + lane*4;
            uint4 p0[4], p1[4];
#pragma unroll
            for (int i=0;i<4;i++) p0[i]=A[i*32];
#pragma unroll
            for (int i=0;i<4;i++) p1[i]=A[(4+i)*32];
#pragma unroll 1
            for (int kb=0;kb<64;kb+=8){
#pragma unroll
                for (int i=0;i<4;i++){
                    uint2 w=*(const uint2*)(W+(kb+i)*128);
                    mma16(d, p0[i], w);
                }
                if (kb<56){
#pragma unroll
                    for (int i=0;i<4;i++) p0[i]=A[(kb+8+i)*32];
                }
#pragma unroll
                for (int i=0;i<4;i++){
                    uint2 w=*(const uint2*)(W+(kb+4+i)*128);
                    mma16(d, p1[i], w);
                }
                if (kb<56){
#pragma unroll
                    for (int i=0;i<4;i++) p1[i]=A[(kb+12+i)*32];
                }
            }
            float* rg = sg;   // 8 tiles x 128 floats = 4KB scratch
            if (kh) *(float4*)(rg + tt*128 + lane*4) = make_float4(d[0],d[1],d[2],d[3]);
            __syncthreads();
            if (!kh){
                float4 q = *(const float4*)(rg + tt*128 + lane*4);
                d[0]+=q.x; d[1]+=q.y; d[2]+=q.z; d[3]+=q.w;
                int r1=lane>>2, c=2*(lane&3);
                int b1 = bgrp*128 + tt*16 + r1, b2 = b1+8;
                float o0=sigm(d[0]+bs[32+c]), o1=sigm(d[1]+bs[33+c]);
                float o2=sigm(d[2]+bs[32+c]), o3=sigm(d[3]+bs[33+c]);
                *(float2*)(out + ((size_t)step*256+b1)*512 + j0m+c) = make_float2(o0,o1);
                *(float2*)(out + ((size_t)step*256+b2)*512 + j0m+c) = make_float2(o2,o3);
                *(__half2*)(g_xA + afx(j0m+c, b1, 32)) = __floats2half2_rn(o0,o1);
                *(__half2*)(g_xA + afx(j0m+c, b2, 32)) = __floats2half2_rn(o2,o3);
            }
        }
        gbar();
        lstm_phase(0,p,g_xA,  w0S, bs,    sgw, u0, wt, lane);
        gbar();
        lstm_phase(1,p,g_x1A, w1S, bs+16, sgw, u0, wt, lane);
        gbar();
    }
}

extern "C" void kernel_launch(void* const* d_in, const int* in_sizes, int n_in,
                              void* d_out, int out_size)
{
    cudaFuncSetAttribute(dec_kernel, cudaFuncAttributeMaxDynamicSharedMemorySize, SMEMSZ);
    dec_kernel<<<NBLK, NTHR, SMEMSZ>>>(
        (const float*)d_in[0], (const float*)d_in[1], (const float*)d_in[2],
        (const float*)d_in[3], (const float*)d_in[4], (const float*)d_in[5],
        (const float*)d_in[6], (const float*)d_in[7], (const float*)d_in[8],
        (const float*)d_in[9], (const float*)d_in[10], (const float*)d_in[11],
        (const float*)d_in[12], (float*)d_out);
}

// round 13
// speedup vs baseline: 3.4445x; 1.4317x over previous
#include <cuda_runtime.h>
#include <cuda_fp16.h>
#include <math.h>

#define NBLK 128
#define NTHR 512
typedef unsigned int u32;

// activation tensors in fp16 A-fragment layout: tiles [bt][kt16][256 halves]
__device__ __align__(16) __half g_fcA[16*128*256];   // fc_in, K=2048
__device__ __align__(16) __half g_xA [16*32*256];    // map out, K=512
__device__ __align__(16) __half g_x1A[16*32*256];    // layer0 h2 (pre-tanh)
__device__ __align__(16) __half g_hA [4][16*32*256]; // tanh(h) [l*2+parity]
__device__ __align__(16) float  g_cT [2*512*256];    // c carry (fp32, linear)
__device__ unsigned g_cnt=0, g_gen=0;

#define OFF_WMAP 0        // 64KB map W: [kt128][nt2][128 halves], 16 cols
#define OFF_WL0  65536    // 64KB lstm0: [kt64][nt4][128], 32 gate rows (8 units)
#define OFF_WL1  131072   // 64KB lstm1
#define OFF_BS   196608   // 80 floats: [0:32) l0, [32:64) l1, [64:80) map
#define OFF_SC   197120   // scratch: gate tile 8*16*37*4=18944 / map reduce / init
#define SMEMSZ   216064

__device__ __forceinline__ int afx(int k, int b, int Kt16){
    return (((b>>4)*Kt16 + (k>>4))<<8) + (((b&7)*4 + ((k&7)>>1))<<3)
         + (((k>>3)&1)<<2) + (((b>>3)&1)<<1) + (k&1);
}
__device__ __forceinline__ float sigm(float x){ return 1.f/(1.f+__expf(-x)); }

__device__ __forceinline__ void mma16(float* d, uint4 a, uint2 b){
    asm("mma.sync.aligned.m16n8k16.row.col.f32.f16.f16.f32 {%0,%1,%2,%3},{%4,%5,%6,%7},{%8,%9},{%0,%1,%2,%3};"
        : "+f"(d[0]),"+f"(d[1]),"+f"(d[2]),"+f"(d[3])
        : "r"(a.x),"r"(a.y),"r"(a.z),"r"(a.w),"r"(b.x),"r"(b.y));
}

__device__ __forceinline__ void gbar(){
    __syncthreads();
    if (threadIdx.x == 0){
        __threadfence();
        unsigned gen = *(volatile unsigned*)&g_gen;
        if (atomicAdd(&g_cnt,1u) == NBLK-1){ g_cnt=0u; __threadfence(); atomicExch(&g_gen, gen+1u); }
        else while (*(volatile unsigned*)&g_gen == gen) __nanosleep(32);
    }
    __syncthreads();
    __threadfence();
}

// LSTM layer: block owns 8 units (32 gate rows = 4 n-tiles) x 128 batches.
// Warp = (bt 0..7, xh): xh=0 x-gemm, xh=1 h-gemm; combine in smem gate tile.
__device__ __forceinline__ void lstm_phase(int l, int p, const __half* xA, const __half* wS,
    const float* bsl, float* gt, int u0, int B0, int wt, int lane, int t)
{
    const int bt = wt & 7, xh = wt >> 3;
    const int btg = (B0>>4) + bt;
    float d[16];
#pragma unroll
    for (int i=0;i<16;i++) d[i]=0.f;
    const uint4* A = (const uint4*)((xh ? g_hA[l*2+p] : xA) + (size_t)btg*32*256) + lane;
    const __half* W = wS + xh*32*4*128 + lane*4;

    uint4 p0[4], p1[4];
#pragma unroll
    for (int i=0;i<4;i++){ p0[i]=A[i*32]; p1[i]=A[(4+i)*32]; }
#pragma unroll 1
    for (int kb=0; kb<32; kb+=8){
#pragma unroll
        for (int i=0;i<4;i++){
            const int kt=kb+i;
#pragma unroll
            for (int nt=0;nt<4;nt++){
                uint2 w=*(const uint2*)(W + (kt*4+nt)*128);
                mma16(d+nt*4, p0[i], w);
            }
        }
        if (kb<24){
#pragma unroll
            for (int i=0;i<4;i++) p0[i]=A[(kb+8+i)*32];
        }
#pragma unroll
        for (int i=0;i<4;i++){
            const int kt=kb+4+i;
#pragma unroll
            for (int nt=0;nt<4;nt++){
                uint2 w=*(const uint2*)(W + (kt*4+nt)*128);
                mma16(d+nt*4, p1[i], w);
            }
        }
        if (kb<24){
#pragma unroll
            for (int i=0;i<4;i++) p1[i]=A[(kb+12+i)*32];
        }
    }

    float* gb = gt + bt*16*37;
    const int r1=lane>>2, c=2*(lane&3);
    if (xh){
#pragma unroll
        for (int nt=0;nt<4;nt++){
            gb[r1*37 + nt*8 + c]       = d[nt*4+0];
            gb[r1*37 + nt*8 + c+1]     = d[nt*4+1];
            gb[(r1+8)*37 + nt*8 + c]   = d[nt*4+2];
            gb[(r1+8)*37 + nt*8 + c+1] = d[nt*4+3];
        }
    }
    __syncthreads();
    if (!xh){
#pragma unroll
        for (int nt=0;nt<4;nt++){
            gb[r1*37 + nt*8 + c]       += d[nt*4+0];
            gb[r1*37 + nt*8 + c+1]     += d[nt*4+1];
            gb[(r1+8)*37 + nt*8 + c]   += d[nt*4+2];
            gb[(r1+8)*37 + nt*8 + c+1] += d[nt*4+3];
        }
    }
    __syncthreads();
    // cell update: 8u x 128b = 1024 cells, 2 per thread
#pragma unroll
    for (int q=0;q<2;q++){
        int cidx = t + q*512;
        int u = cidx>>7, bl = cidx&127;
        const float* gr = gt + ((bl>>4)*16 + (bl&15))*37;
        float gi=gr[u]+bsl[u], gf=gr[8+u]+bsl[8+u], gg=gr[16+u]+bsl[16+u], go=gr[24+u]+bsl[24+u];
        int j = u0+u, b = B0+bl;
        size_t ci = (size_t)l*131072 + (size_t)j*256 + b;
        float c2 = sigm(gf)*g_cT[ci] + sigm(gi)*tanhf(gg);
        float h2 = sigm(go)*tanhf(c2);
        float th=tanhf(h2), tc=tanhf(c2);
        g_cT[ci]=tc;
        g_hA[l*2+(p^1)][afx(j,b,32)]=__float2half(th);
        if (l==0) g_x1A[afx(j,b,32)]=__float2half(h2);
        int rf=l*128+(b>>1), ch=(b&1)*1024+j;
        g_fcA[afx(ch,rf,128)]=__float2half(th);
        g_fcA[afx(ch+512,rf,128)]=__float2half(tc);
    }
}

extern "C" __global__ void __launch_bounds__(NTHR,1)
dec_kernel(const float* __restrict__ latent, const float* __restrict__ fc_w,
    const float* __restrict__ fc_b, const float* __restrict__ map_w, const float* __restrict__ map_b,
    const float* __restrict__ wih0, const float* __restrict__ whh0, const float* __restrict__ bih0,
    const float* __restrict__ bhh0, const float* __restrict__ wih1, const float* __restrict__ whh1,
    const float* __restrict__ bih1, const float* __restrict__ bhh1, float* __restrict__ out)
{
    extern __shared__ unsigned char smem[];
    __half* wmapS=(__half*)(smem+OFF_WMAP);
    __half* w0S  =(__half*)(smem+OFF_WL0);
    __half* w1S  =(__half*)(smem+OFF_WL1);
    float*  bs   =(float*) (smem+OFF_BS);
    float*  sc   =(float*) (smem+OFF_SC);
    const int t=threadIdx.x, blk=blockIdx.x;
    const int wt=t>>5, lane=t&31;
    const int u0=(blk>>1)*8, B0=(blk&1)*128;         // lstm: 8 units x 128 batches
    const int j0m=(blk>>2)*16, B0m=(blk&3)*64;       // map: 16 cols x 64 batches

    // ---- weights -> smem, B-frag half layout ----
    for (int idx=t; idx<32768; idx+=NTHR){           // map: [kt128][nt2][128]
        int kt=idx>>8, rem=idx&255, nt=rem>>7, r2=rem&127, ln=r2>>2, q2=r2&3, sl=q2>>1, klo=q2&1;
        int nr=ln>>2, tn=ln&3;
        int col=j0m + nt*8 + nr, k=kt*16 + sl*8 + tn*2 + klo;
        wmapS[idx]=__float2half(map_w[(size_t)col*2048 + k]);
    }
    for (int idx=t; idx<32768; idx+=NTHR){           // lstm: [kt64][nt4][128]
        int kt=idx>>9, rem=idx&511, nt=rem>>7, r2=rem&127, ln=r2>>2, q2=r2&3, sl=q2>>1, klo=q2&1;
        int nr=ln>>2, tn=ln&3;
        int rr=nt*8+nr, k=kt*16 + sl*8 + tn*2 + klo;
        int row=(rr>>3)*512 + u0 + (rr&7);
        w0S[idx]=__float2half(k<512? wih0[(size_t)row*512+k] : whh0[(size_t)row*512+k-512]);
        w1S[idx]=__float2half(k<512? wih1[(size_t)row*512+k] : whh1[(size_t)row*512+k-512]);
    }
    if (t<32){ int row=(t>>3)*512 + u0 + (t&7); bs[t]=bih0[row]+bhh0[row]; bs[32+t]=bih1[row]+bhh1[row]; }
    if (t<16) bs[64+t]=map_b[j0m+t];
    __syncthreads();

    // ---- init: dec = tanh(latent @ fc_w.T + fc_b), scatter to frag tensors ----
    {
        float* sL=sc;  int b0=blk*2;
        for (int idx=t; idx<512; idx+=NTHR)
            sL[idx]=latent[(size_t)(b0+(idx>>8))*256 + (idx&255)];
        __syncthreads();
        int bi=t>>8, jb=(t&255)*8, b=b0+bi;
        const float* la=sL+bi*256;
        for (int m=0;m<8;m++){
            int jj=jb+m; float s=fc_b[jj];
            const float4* wr=(const float4*)(fc_w+(size_t)jj*256);
#pragma unroll 4
            for (int k4=0;k4<64;k4++){
                float4 w=wr[k4];
                s += la[k4*4]*w.x + la[k4*4+1]*w.y + la[k4*4+2]*w.z + la[k4*4+3]*w.w;
            }
            float val=tanhf(s);
            int l=b>>7, b2=((b&127)*2 + (jj>>10)), jj2=jj&1023;
            if (jj2<512) g_hA[l*2][afx(jj2,b2,32)]=__float2half(val);
            else         g_cT[(size_t)l*131072 + (size_t)(jj2-512)*256 + b2]=val;
            int rf=l*128+(b2>>1), ch=(b2&1)*1024+jj2;
            g_fcA[afx(ch,rf,128)]=__float2half(val);
        }
        __syncthreads();
    }
    gbar();

    // ================= 256 sequential steps =================
    for (int step=0; step<256; step++){
        int p=step&1;
        // ---- map: 16 cols x 64 batches; warp = (bt 0..3, kh 0..3); K=2048 split 4-way ----
        {
            const int btm = wt&3, kh = wt>>2;
            const int btg = (B0m>>4) + btm;
            float d[8]={0,0,0,0,0,0,0,0};
            const uint4* A=(const uint4*)(g_fcA + ((size_t)btg*128 + kh*32)*256)+lane;
            const __half* W=wmapS + kh*32*2*128 + lane*4;
            uint4 p0[4], p1[4];
#pragma unroll
            for (int i=0;i<4;i++){ p0[i]=A[i*32]; p1[i]=A[(4+i)*32]; }
#pragma unroll 1
            for (int kb=0;kb<32;kb+=8){
#pragma unroll
                for (int i=0;i<4;i++){
                    const int kt=kb+i;
#pragma unroll
                    for (int nt=0;nt<2;nt++){
                        uint2 w=*(const uint2*)(W+(kt*2+nt)*128);
                        mma16(d+nt*4, p0[i], w);
                    }
                }
                if (kb<24){
#pragma unroll
                    for (int i=0;i<4;i++) p0[i]=A[(kb+8+i)*32];
                }
#pragma unroll
                for (int i=0;i<4;i++){
                    const int kt=kb+4+i;
#pragma unroll
                    for (int nt=0;nt<2;nt++){
                        uint2 w=*(const uint2*)(W+(kt*2+nt)*128);
                        mma16(d+nt*4, p1[i], w);
                    }
                }
                if (kb<24){
#pragma unroll
                    for (int i=0;i<4;i++) p1[i]=A[(kb+12+i)*32];
                }
            }
            if (kh){
                float4* dst=(float4*)(sc + ((kh-1)*4 + btm)*256 + lane*8);
                dst[0]=make_float4(d[0],d[1],d[2],d[3]);
                dst[1]=make_float4(d[4],d[5],d[6],d[7]);
            }
            __syncthreads();
            if (!kh){
#pragma unroll
                for (int g=0;g<3;g++){
                    const float4* src=(const float4*)(sc + (g*4 + btm)*256 + lane*8);
                    float4 q0=src[0], q1=src[1];
                    d[0]+=q0.x; d[1]+=q0.y; d[2]+=q0.z; d[3]+=q0.w;
                    d[4]+=q1.x; d[5]+=q1.y; d[6]+=q1.z; d[7]+=q1.w;
                }
                int r1=lane>>2, c=2*(lane&3);
                int b1 = B0m + btm*16 + r1, b2 = b1+8;
#pragma unroll
                for (int nt=0;nt<2;nt++){
                    int col = j0m + nt*8 + c;
                    float o0=sigm(d[nt*4+0]+bs[64+nt*8+c]), o1=sigm(d[nt*4+1]+bs[64+nt*8+c+1]);
                    float o2=sigm(d[nt*4+2]+bs[64+nt*8+c]), o3=sigm(d[nt*4+3]+bs[64+nt*8+c+1]);
                    *(float2*)(out + ((size_t)step*256+b1)*512 + col) = make_float2(o0,o1);
                    *(float2*)(out + ((size_t)step*256+b2)*512 + col) = make_float2(o2,o3);
                    *(__half2*)(g_xA + afx(col, b1, 32)) = __floats2half2_rn(o0,o1);
                    *(__half2*)(g_xA + afx(col, b2, 32)) = __floats2half2_rn(o2,o3);
                }
            }
        }
        gbar();
        lstm_phase(0,p,g_xA,  w0S, bs,    sc, u0, B0, wt, lane, t);
        gbar();
        lstm_phase(1,p,g_x1A, w1S, bs+32, sc, u0, B0, wt, lane, t);
        gbar();
    }
}

extern "C" void kernel_launch(void* const* d_in, const int* in_sizes, int n_in,
                              void* d_out, int out_size)
{
    cudaFuncSetAttribute(dec_kernel, cudaFuncAttributeMaxDynamicSharedMemorySize, SMEMSZ);
    dec_kernel<<<NBLK, NTHR, SMEMSZ>>>(
        (const float*)d_in[0], (const float*)d_in[1], (const float*)d_in[2],
        (const float*)d_in[3], (const float*)d_in[4], (const float*)d_in[5],
        (const float*)d_in[6], (const float*)d_in[7], (const float*)d_in[8],
        (const float*)d_in[9], (const float*)d_in[10], (const float*)d_in[11],
        (const float*)d_in[12], (float*)d_out);
}

// round 15
// speedup vs baseline: 3.7839x; 1.0985x over previous
#include <cuda_runtime.h>
#include <cuda_fp16.h>
#include <math.h>

#define NBLK 128
#define NTHR 768
typedef unsigned int u32;

// activation tensors in fp16 A-fragment layout: tiles [bt][kt16][256 halves]
__device__ __align__(16) __half g_fcA[16*128*256];   // fc_in, K=2048
__device__ __align__(16) __half g_xA [16*32*256];    // map out, K=512
__device__ __align__(16) __half g_x1A[16*32*256];    // layer0 h2 (pre-tanh)
__device__ __align__(16) __half g_hA [4][16*32*256]; // tanh(h) [l*2+parity]
__device__ __align__(16) float  g_cT [2*512*256];    // c carry fp32, [l][b][j]
__device__ unsigned g_cnt=0, g_gen=0;

#define OFF_WMAP 0        // 64KB map W: [kt128][nt2][128 halves], 16 cols
#define OFF_WL0  65536    // 64KB lstm0: [kt64][nt4][128], 32 gate rows (8 units)
#define OFF_WL1  131072   // 64KB lstm1
#define OFF_BS   196608   // 80 floats
#define OFF_SC   197120   // scratch: gate tile 8*16*37*4 / map reduce 5*4*256*4 / init
#define SMEMSZ   217600

__device__ __forceinline__ int afx(int k, int b, int Kt16){
    return (((b>>4)*Kt16 + (k>>4))<<8) + (((b&7)*4 + ((k&7)>>1))<<3)
         + (((k>>3)&1)<<2) + (((b>>3)&1)<<1) + (k&1);
}
__device__ __forceinline__ float tanhap(float x){ float y; asm("tanh.approx.f32 %0,%1;":"=f"(y):"f"(x)); return y; }
__device__ __forceinline__ float sigm(float x){ return 0.5f + 0.5f*tanhap(0.5f*x); }

__device__ __forceinline__ void mma16(float* d, uint4 a, uint2 b){
    asm("mma.sync.aligned.m16n8k16.row.col.f32.f16.f16.f32 {%0,%1,%2,%3},{%4,%5,%6,%7},{%8,%9},{%0,%1,%2,%3};"
        : "+f"(d[0]),"+f"(d[1]),"+f"(d[2]),"+f"(d[3])
        : "r"(a.x),"r"(a.y),"r"(a.z),"r"(a.w),"r"(b.x),"r"(b.y));
}

// fully-unrolled pipelined GEMM over NG groups of 4 k-tiles, NTT n-tiles.
// A: lane-offset uint4 base (tile kt at +kt*32); W: lane-offset half base ([kt][NTT][128]).
template<int NG, int NTT>
__device__ __forceinline__ void gemm_t(const uint4* A, const __half* W, float* d){
    uint4 pa[2][4];
#pragma unroll
    for (int i=0;i<4;i++) pa[0][i] = A[i*32];
#pragma unroll
    for (int i=0;i<4;i++) pa[1][i] = (NG>1)? A[(4+i)*32] : pa[0][i];
#pragma unroll
    for (int g=0; g<NG; g++){
#pragma unroll
        for (int i=0;i<4;i++){
            const int kt = g*4+i;
#pragma unroll
            for (int nt=0; nt<NTT; nt++){
                uint2 w = *(const uint2*)(W + (kt*NTT+nt)*128);
                mma16(d+nt*4, pa[g&1][i], w);
            }
        }
        if (g+2 < NG){
#pragma unroll
            for (int i=0;i<4;i++) pa[g&1][i] = A[((g+2)*4+i)*32];
        }
    }
}

__device__ __forceinline__ void gbar(){
    __syncthreads();
    if (threadIdx.x == 0){
        __threadfence();
        unsigned gen = *(volatile unsigned*)&g_gen;
        if (atomicAdd(&g_cnt,1u) == NBLK-1){ g_cnt=0u; __threadfence(); atomicExch(&g_gen, gen+1u); }
        else while (*(volatile unsigned*)&g_gen == gen) __nanosleep(32);
    }
    __syncthreads();
    __threadfence();
}

// LSTM layer: block owns 8 units (32 gate rows = 4 n-tiles) x 128 batches.
// 24 warps = 8 bt x 3 k-splits over combined 64 kt (x:0..31, h:32..63), groups (6,5,5).
__device__ __forceinline__ void lstm_phase(int l, int p, const __half* xA, const __half* wS,
    const float* bsl, float* gt, int u0, int B0, int wt, int lane, int t)
{
    const int bt = wt & 7, ks = wt >> 3;
    const int btg = (B0>>4) + bt;
    float d[16];
#pragma unroll
    for (int i=0;i<16;i++) d[i]=0.f;
    const uint4* Ax = (const uint4*)(xA + (size_t)btg*32*256) + lane;
    const uint4* Ah = (const uint4*)(g_hA[l*2+p] + (size_t)btg*32*256) + lane;
    const __half* W = wS + lane*4;

    if (ks==0){
        gemm_t<6,4>(Ax, W, d);                         // x kt [0,24)
    } else if (ks==1){
        gemm_t<2,4>(Ax + 24*32, W + 24*4*128, d);      // x kt [24,32)
        gemm_t<3,4>(Ah,         W + 32*4*128, d);      // h kt [0,12)
    } else {
        gemm_t<5,4>(Ah + 12*32, W + 44*4*128, d);      // h kt [12,32)
    }

    float* gb = gt + bt*16*37;
    const int r1=lane>>2, c=2*(lane&3);
    if (ks==0){
#pragma unroll
        for (int nt=0;nt<4;nt++){
            gb[r1*37 + nt*8 + c]       = d[nt*4+0];
            gb[r1*37 + nt*8 + c+1]     = d[nt*4+1];
            gb[(r1+8)*37 + nt*8 + c]   = d[nt*4+2];
            gb[(r1+8)*37 + nt*8 + c+1] = d[nt*4+3];
        }
    }
    __syncthreads();
    if (ks==1){
#pragma unroll
        for (int nt=0;nt<4;nt++){
            gb[r1*37 + nt*8 + c]       += d[nt*4+0];
            gb[r1*37 + nt*8 + c+1]     += d[nt*4+1];
            gb[(r1+8)*37 + nt*8 + c]   += d[nt*4+2];
            gb[(r1+8)*37 + nt*8 + c+1] += d[nt*4+3];
        }
    }
    __syncthreads();
    if (ks==2){
#pragma unroll
        for (int nt=0;nt<4;nt++){
            gb[r1*37 + nt*8 + c]       += d[nt*4+0];
            gb[r1*37 + nt*8 + c+1]     += d[nt*4+1];
            gb[(r1+8)*37 + nt*8 + c]   += d[nt*4+2];
            gb[(r1+8)*37 + nt*8 + c+1] += d[nt*4+3];
        }
    }
    __syncthreads();
    // cell update: 512 pair-tasks (unit pair x 128 batches)
    if (t < 512){
        const int up = t>>7, bl = t&127;
        const int u = up*2, j = u0+u, b = B0+bl;
        const float* gr = gt + bl*37;
        float2 co = *(const float2*)(g_cT + (size_t)l*131072 + (size_t)b*512 + j);
        float thv[2], tcv[2], h2v[2];
#pragma unroll
        for (int i=0;i<2;i++){
            int uu = u+i;
            float gi=gr[uu]+bsl[uu], gf=gr[8+uu]+bsl[8+uu];
            float gg=gr[16+uu]+bsl[16+uu], go=gr[24+uu]+bsl[24+uu];
            float cold = i? co.y : co.x;
            float c2 = sigm(gf)*cold + sigm(gi)*tanhap(gg);
            float h2 = sigm(go)*tanhap(c2);
            h2v[i]=h2; thv[i]=tanhap(h2); tcv[i]=tanhap(c2);
        }
        *(float2*)(g_cT + (size_t)l*131072 + (size_t)b*512 + j) = make_float2(tcv[0],tcv[1]);
        *(__half2*)(g_hA[l*2+(p^1)] + afx(j,b,32)) = __floats2half2_rn(thv[0],thv[1]);
        if (l==0) *(__half2*)(g_x1A + afx(j,b,32)) = __floats2half2_rn(h2v[0],h2v[1]);
        int rf=l*128+(b>>1), ch=(b&1)*1024+j;
        *(__half2*)(g_fcA + afx(ch,rf,128))     = __floats2half2_rn(thv[0],thv[1]);
        *(__half2*)(g_fcA + afx(ch+512,rf,128)) = __floats2half2_rn(tcv[0],tcv[1]);
    }
}

extern "C" __global__ void __launch_bounds__(NTHR,1)
dec_kernel(const float* __restrict__ latent, const float* __restrict__ fc_w,
    const float* __restrict__ fc_b, const float* __restrict__ map_w, const float* __restrict__ map_b,
    const float* __restrict__ wih0, const float* __restrict__ whh0, const float* __restrict__ bih0,
    const float* __restrict__ bhh0, const float* __restrict__ wih1, const float* __restrict__ whh1,
    const float* __restrict__ bih1, const float* __restrict__ bhh1, float* __restrict__ out)
{
    extern __shared__ unsigned char smem[];
    __half* wmapS=(__half*)(smem+OFF_WMAP);
    __half* w0S  =(__half*)(smem+OFF_WL0);
    __half* w1S  =(__half*)(smem+OFF_WL1);
    float*  bs   =(float*) (smem+OFF_BS);
    float*  sc   =(float*) (smem+OFF_SC);
    const int t=threadIdx.x, blk=blockIdx.x;
    const int wt=t>>5, lane=t&31;
    const int u0=(blk>>1)*8, B0=(blk&1)*128;         // lstm: 8 units x 128 batches
    const int j0m=(blk>>2)*16, B0m=(blk&3)*64;       // map: 16 cols x 64 batches

    // ---- weights -> smem, B-frag half layout ----
    for (int idx=t; idx<32768; idx+=NTHR){           // map: [kt128][nt2][128]
        int kt=idx>>8, rem=idx&255, nt=rem>>7, r2=rem&127, ln=r2>>2, q2=r2&3, sl=q2>>1, klo=q2&1;
        int nr=ln>>2, tn=ln&3;
        int col=j0m + nt*8 + nr, k=kt*16 + sl*8 + tn*2 + klo;
        wmapS[idx]=__float2half(map_w[(size_t)col*2048 + k]);
    }
    for (int idx=t; idx<32768; idx+=NTHR){           // lstm: [kt64][nt4][128]
        int kt=idx>>9, rem=idx&511, nt=rem>>7, r2=rem&127, ln=r2>>2, q2=r2&3, sl=q2>>1, klo=q2&1;
        int nr=ln>>2, tn=ln&3;
        int rr=nt*8+nr, k=kt*16 + sl*8 + tn*2 + klo;
        int row=(rr>>3)*512 + u0 + (rr&7);
        w0S[idx]=__float2half(k<512? wih0[(size_t)row*512+k] : whh0[(size_t)row*512+k-512]);
        w1S[idx]=__float2half(k<512? wih1[(size_t)row*512+k] : whh1[(size_t)row*512+k-512]);
    }
    if (t<32){ int row=(t>>3)*512 + u0 + (t&7); bs[t]=bih0[row]+bhh0[row]; bs[32+t]=bih1[row]+bhh1[row]; }
    if (t<16) bs[64+t]=map_b[j0m+t];
    __syncthreads();

    // ---- init: dec = tanh(latent @ fc_w.T + fc_b), scatter to frag tensors ----
    {
        float* sL=sc;  int b0=blk*2;
        for (int idx=t; idx<512; idx+=NTHR)
            sL[idx]=latent[(size_t)(b0+(idx>>8))*256 + (idx&255)];
        __syncthreads();
        if (t < 512){
            int bi = t>>8, jb = (t&255)*8, b = b0+bi;
            const float* la = sL+bi*256;
            for (int m=0;m<8;m++){
                int jj=jb+m; float s=fc_b[jj];
                const float4* wr=(const float4*)(fc_w+(size_t)jj*256);
#pragma unroll 4
                for (int k4=0;k4<64;k4++){
                    float4 w=wr[k4];
                    s += la[k4*4]*w.x + la[k4*4+1]*w.y + la[k4*4+2]*w.z + la[k4*4+3]*w.w;
                }
                float val=tanhf(s);
                int l=b>>7, b2=((b&127)*2 + (jj>>10)), jj2=jj&1023;
                if (jj2<512) g_hA[l*2][afx(jj2,b2,32)]=__float2half(val);
                else         g_cT[(size_t)l*131072 + (size_t)b2*512 + (jj2-512)]=val;
                int rf=l*128+(b2>>1), ch=(b2&1)*1024+jj2;
                g_fcA[afx(ch,rf,128)]=__float2half(val);
            }
        }
        __syncthreads();
    }
    gbar();

    // ================= 256 sequential steps =================
    for (int step=0; step<256; step++){
        int p=step&1;
        // ---- map: 16 cols x 64 batches; warp = (bt 0..3, ks 0..5); K=2048 split 6-way ----
        {
            const int btm = wt & 3, ksm = wt >> 2;
            const int btg = (B0m>>4) + btm;
            float d[8]={0,0,0,0,0,0,0,0};
            const uint4* A=(const uint4*)(g_fcA + (size_t)btg*128*256)+lane;
            const __half* W=wmapS + lane*4;
            switch (ksm){
                case 0: gemm_t<6,2>(A,         W,            d); break;
                case 1: gemm_t<6,2>(A+ 24*32,  W+ 24*2*128,  d); break;
                case 2: gemm_t<5,2>(A+ 48*32,  W+ 48*2*128,  d); break;
                case 3: gemm_t<5,2>(A+ 68*32,  W+ 68*2*128,  d); break;
                case 4: gemm_t<5,2>(A+ 88*32,  W+ 88*2*128,  d); break;
                default:gemm_t<5,2>(A+108*32,  W+108*2*128,  d); break;
            }
            if (ksm){
                float4* dst=(float4*)(sc + ((ksm-1)*4 + btm)*256 + lane*8);
                dst[0]=make_float4(d[0],d[1],d[2],d[3]);
                dst[1]=make_float4(d[4],d[5],d[6],d[7]);
            }
            __syncthreads();
            if (!ksm){
#pragma unroll
                for (int g=0;g<5;g++){
                    const float4* src=(const float4*)(sc + (g*4 + btm)*256 + lane*8);
                    float4 q0=src[0], q1=src[1];
                    d[0]+=q0.x; d[1]+=q0.y; d[2]+=q0.z; d[3]+=q0.w;
                    d[4]+=q1.x; d[5]+=q1.y; d[6]+=q1.z; d[7]+=q1.w;
                }
                int r1=lane>>2, c=2*(lane&3);
                int b1 = B0m + btm*16 + r1, b2 = b1+8;
#pragma unroll
                for (int nt=0;nt<2;nt++){
                    int col = j0m + nt*8 + c;
                    float o0=sigm(d[nt*4+0]+bs[64+nt*8+c]), o1=sigm(d[nt*4+1]+bs[64+nt*8+c+1]);
                    float o2=sigm(d[nt*4+2]+bs[64+nt*8+c]), o3=sigm(d[nt*4+3]+bs[64+nt*8+c+1]);
                    *(float2*)(out + ((size_t)step*256+b1)*512 + col) = make_float2(o0,o1);
                    *(float2*)(out + ((size_t)step*256+b2)*512 + col) = make_float2(o2,o3);
                    *(__half2*)(g_xA + afx(col, b1, 32)) = __floats2half2_rn(o0,o1);
                    *(__half2*)(g_xA + afx(col, b2, 32)) = __floats2half2_rn(o2,o3);
                }
            }
        }
        gbar();
        lstm_phase(0,p,g_xA,  w0S, bs,    sc, u0, B0, wt, lane, t);
        gbar();
        lstm_phase(1,p,g_x1A, w1S, bs+32, sc, u0, B0, wt, lane, t);
        gbar();
    }
}

extern "C" void kernel_launch(void* const* d_in, const int* in_sizes, int n_in,
                              void* d_out, int out_size)
{
    cudaFuncSetAttribute(dec_kernel, cudaFuncAttributeMaxDynamicSharedMemorySize, SMEMSZ);
    dec_kernel<<<NBLK, NTHR, SMEMSZ>>>(
        (const float*)d_in[0], (const float*)d_in[1], (const float*)d_in[2],
        (const float*)d_in[3], (const float*)d_in[4], (const float*)d_in[5],
        (const float*)d_in[6], (const float*)d_in[7], (const float*)d_in[8],
        (const float*)d_in[9], (const float*)d_in[10], (const float*)d_in[11],
        (const float*)d_in[12], (float*)d_out);
}